// round 1
// baseline (speedup 1.0000x reference)
#include <cuda_runtime.h>
#include <cstdint>
#include <cfloat>
#include <cstddef>

#define BQ 2
#define NQ 8192
#define RQ 2048
#define KQ 16
#define COUTQ 128

// ---------------- scratch (no allocations allowed) ----------------
__device__ int   g_nn[BQ * RQ * KQ];          // neighbor indices per rep point
__device__ float g_wt[1280 * COUTQ];          // conv_w transposed: Wt[j][o] = conv_w[o][j]

// ---------------- kernel 1: transpose conv weights ----------------
__global__ void transpose_conv_kernel(const float* __restrict__ cw) {
    int t = blockIdx.x * 256 + threadIdx.x;
    if (t < 1280 * 128) {
        int j = t >> 7, o = t & 127;
        g_wt[t] = __ldg(&cw[o * 1280 + j]);
    }
}

// ---------------- kernel 2: kNN for representative points ----------------
// grid (64, 2): 32 reps per block, blockIdx.y = batch. 256 threads:
// thread = (rep_slot = tid>>3, chunk = tid&7), each scans 1024 candidates.
#define KNN_SMEM_BYTES (NQ * 16 + 256 * 17 * 8)

__global__ __launch_bounds__(256, 1) void knn_kernel(
    const float* __restrict__ points, const int* __restrict__ rep_idx)
{
    extern __shared__ float4 sp[];               // [8192] x,y,z,sq
    float* md = (float*)(sp + NQ);               // [256][17]
    int*   mi = (int*)(md + 256 * 17);           // [256][17]
    const int tid = threadIdx.x;
    const int b   = blockIdx.y;
    const float* P = points + (size_t)b * NQ * 3;

    for (int i = tid; i < NQ; i += 256) {
        float x = P[i * 3 + 0], y = P[i * 3 + 1], z = P[i * 3 + 2];
        // sq = x*x + y*y + z*z (left-to-right like the reference)
        sp[i] = make_float4(x, y, z, fmaf(z, z, fmaf(y, y, x * x)));
    }
    __syncthreads();

    const int rl  = blockIdx.x * 32 + (tid >> 3);
    const int ch  = tid & 7;
    const int rpt = __ldg(&rep_idx[rl]);
    const float4 rp = sp[rpt];

    float bd[17]; int bi[17];
#pragma unroll
    for (int j = 0; j < 17; j++) { bd[j] = FLT_MAX; bi[j] = 0x7fffffff; }

    const int c0 = ch << 10;
    for (int t = 0; t < 1024; ++t) {
        // stagger start per chunk -> conflict-free shared banks; order-independent
        int c = c0 + ((t + ch) & 1023);
        float4 q = sp[c];
        float dot = fmaf(rp.z, q.z, fmaf(rp.y, q.y, rp.x * q.x));
        float d2  = fmaf(-2.f, dot, rp.w + q.w);   // sq_r + sq_c - 2*dot
        if (d2 < bd[16] || (d2 == bd[16] && c < bi[16])) {
            float vd = d2; int vi = c;
#pragma unroll
            for (int j = 0; j < 17; j++) {
                bool sw = (vd < bd[j]) || (vd == bd[j] && vi < bi[j]);
                if (sw) { float td = bd[j]; int ti = bi[j];
                          bd[j] = vd; bi[j] = vi; vd = td; vi = ti; }
            }
        }
    }
#pragma unroll
    for (int j = 0; j < 17; j++) { md[tid * 17 + j] = bd[j]; mi[tid * 17 + j] = bi[j]; }
    __syncthreads();

    // merge 8 sorted lists per rep; drop rank 0 (self), emit ranks 1..16
    if (tid < 32) {
        const int base = tid * 8;
        int ptr[8] = {0, 0, 0, 0, 0, 0, 0, 0};
        const int rloc = blockIdx.x * 32 + tid;
        int* dst = &g_nn[((size_t)b * RQ + rloc) * KQ];
        for (int t = 0; t < 17; ++t) {
            float best = FLT_MAX; int bidx = 0x7fffffff; int bc = -1;
#pragma unroll
            for (int c2 = 0; c2 < 8; c2++) {
                int p = ptr[c2];
                float d = md[(base + c2) * 17 + p];
                int   i2 = mi[(base + c2) * 17 + p];
                if (d < best || (d == best && i2 < bidx)) { best = d; bidx = i2; bc = c2; }
            }
#pragma unroll
            for (int c2 = 0; c2 < 8; c2++) if (c2 == bc) ptr[c2]++;
            if (t > 0) dst[t - 1] = bidx;
        }
    }
}

// ---------------- kernel 3: fused gather + lift + MLP + transform + conv ----------------
// 256 blocks, each handles G=16 groups with 256 threads.
// Shared layout (floats):
//   sH   [16][256]     @ 0       (hidden / T / Tf chunk buffer, reused)
//   sF   [16][1288]    @ 4096    (feat: [16 k][80 c] padded stride 1288/group)
//   sP   [16][48]      @ 24704   (pf rows)
#define MAIN_SMEM_FLOATS (4096 + 16 * 1288 + 768)
#define MAIN_SMEM_BYTES  (MAIN_SMEM_FLOATS * 4)
#define SF_OFF 4096
#define SP_OFF 24704

__global__ __launch_bounds__(256, 2) void main_kernel(
    const float* __restrict__ points,  const float* __restrict__ features,
    const float* __restrict__ lift_w,  const float* __restrict__ lift_b,
    const float* __restrict__ bnl_g,   const float* __restrict__ bnl_b,
    const float* __restrict__ t1_w,    const float* __restrict__ t1_b,
    const float* __restrict__ bn1_g,   const float* __restrict__ bn1_b,
    const float* __restrict__ t2_w,    const float* __restrict__ t2_b,
    const float* __restrict__ bn2_g,   const float* __restrict__ bn2_b,
    const float* __restrict__ t3_w,    const float* __restrict__ t3_b,
    const float* __restrict__ bn3_g,   const float* __restrict__ bn3_b,
    const float* __restrict__ conv_b,  const int* __restrict__ rep_idx,
    float* __restrict__ out_rep, float* __restrict__ out_main)
{
    extern __shared__ float sm[];
    float* sH = sm;
    float* sF = sm + SF_OFF;
    float* sP = sm + SP_OFF;
    const int tid = threadIdx.x;
    const int gg0 = blockIdx.x * 16;

    // ---- gather + lift: thread = (group g, neighbor k) ----
    {
        const int g = tid >> 4, k = tid & 15;
        const int gg = gg0 + g;
        const int b = gg >> 11, rl = gg & 2047;
        const int rpt = __ldg(&rep_idx[rl]);
        const float* rpp = points + ((size_t)b * NQ + rpt) * 3;
        const float rx = __ldg(rpp), ry = __ldg(rpp + 1), rz = __ldg(rpp + 2);
        const int nb = g_nn[gg * KQ + k];
        const float* npp = points + ((size_t)b * NQ + nb) * 3;
        const float px = __ldg(npp) - rx, py = __ldg(npp + 1) - ry, pz = __ldg(npp + 2) - rz;
        sP[g * 48 + k * 3 + 0] = px;
        sP[g * 48 + k * 3 + 1] = py;
        sP[g * 48 + k * 3 + 2] = pz;
        if (k == 0) {
            out_rep[gg * 3 + 0] = rx; out_rep[gg * 3 + 1] = ry; out_rep[gg * 3 + 2] = rz;
        }
        // lifted features -> feat cols [0,16)
        float* fl = &sF[g * 1288 + k * 80];
#pragma unroll
        for (int j = 0; j < 16; j++) {
            float d = fmaf(pz, __ldg(&lift_w[j * 3 + 2]),
                      fmaf(py, __ldg(&lift_w[j * 3 + 1]), px * __ldg(&lift_w[j * 3 + 0])));
            float v = fmaf(d + __ldg(&lift_b[j]), __ldg(&bnl_g[j]), __ldg(&bnl_b[j]));
            fl[j] = fmaxf(v, 0.f);
        }
        // gathered neighbor features -> feat cols [16,80)
        const float4* fr = (const float4*)(features + ((size_t)b * NQ + nb) * 64);
        float4* fd = (float4*)(fl + 16);
#pragma unroll
        for (int q = 0; q < 16; q++) fd[q] = __ldg(fr + q);
    }
    __syncthreads();

    const int i = tid;   // output neuron for the three MLP GEMMs
    float acc[16];

    // ---- t1: [16 groups x 48] @ t1_w.T -> H[16][256], bn+relu ----
    {
#pragma unroll
        for (int g2 = 0; g2 < 16; g2++) acc[g2] = 0.f;
        const float4* w4 = (const float4*)(t1_w + i * 48);
#pragma unroll
        for (int jj = 0; jj < 12; ++jj) {
            const float4 w = __ldg(w4 + jj);
#pragma unroll
            for (int g2 = 0; g2 < 16; ++g2) {
                const float4 h = *(const float4*)&sP[g2 * 48 + jj * 4];
                acc[g2] = fmaf(w.x, h.x, acc[g2]); acc[g2] = fmaf(w.y, h.y, acc[g2]);
                acc[g2] = fmaf(w.z, h.z, acc[g2]); acc[g2] = fmaf(w.w, h.w, acc[g2]);
            }
        }
        const float tb = __ldg(&t1_b[i]), bg = __ldg(&bn1_g[i]), bb = __ldg(&bn1_b[i]);
#pragma unroll
        for (int g2 = 0; g2 < 16; g2++)
            sH[g2 * 256 + i] = fmaxf(fmaf(acc[g2] + tb, bg, bb), 0.f);
    }
    __syncthreads();

    // ---- t2: H @ t2_w.T, bn+relu (in-place with sync fence) ----
    {
#pragma unroll
        for (int g2 = 0; g2 < 16; g2++) acc[g2] = 0.f;
        const float4* w4 = (const float4*)(t2_w + i * 256);
#pragma unroll 4
        for (int jj = 0; jj < 64; ++jj) {
            const float4 w = __ldg(w4 + jj);
#pragma unroll
            for (int g2 = 0; g2 < 16; ++g2) {
                const float4 h = *(const float4*)&sH[g2 * 256 + jj * 4];
                acc[g2] = fmaf(w.x, h.x, acc[g2]); acc[g2] = fmaf(w.y, h.y, acc[g2]);
                acc[g2] = fmaf(w.z, h.z, acc[g2]); acc[g2] = fmaf(w.w, h.w, acc[g2]);
            }
        }
        const float tb = __ldg(&t2_b[i]), bg = __ldg(&bn2_g[i]), bb = __ldg(&bn2_b[i]);
        __syncthreads();   // all reads of sH done before overwrite
#pragma unroll
        for (int g2 = 0; g2 < 16; g2++)
            sH[g2 * 256 + i] = fmaxf(fmaf(acc[g2] + tb, bg, bb), 0.f);
    }
    __syncthreads();

    // ---- t3: H @ t3_w.T, bn (no relu) -> T[16 groups][16][16] stored in sH ----
    {
#pragma unroll
        for (int g2 = 0; g2 < 16; g2++) acc[g2] = 0.f;
        const float4* w4 = (const float4*)(t3_w + i * 256);
#pragma unroll 4
        for (int jj = 0; jj < 64; ++jj) {
            const float4 w = __ldg(w4 + jj);
#pragma unroll
            for (int g2 = 0; g2 < 16; ++g2) {
                const float4 h = *(const float4*)&sH[g2 * 256 + jj * 4];
                acc[g2] = fmaf(w.x, h.x, acc[g2]); acc[g2] = fmaf(w.y, h.y, acc[g2]);
                acc[g2] = fmaf(w.z, h.z, acc[g2]); acc[g2] = fmaf(w.w, h.w, acc[g2]);
            }
        }
        const float tb = __ldg(&t3_b[i]), bg = __ldg(&bn3_g[i]), bb = __ldg(&bn3_b[i]);
        __syncthreads();
#pragma unroll
        for (int g2 = 0; g2 < 16; g2++)
            sH[g2 * 256 + i] = fmaf(acc[g2] + tb, bg, bb);
    }
    __syncthreads();

    // ---- load per-thread T row into registers: thread = (gT, aT) ----
    const int aT = tid & 15, gT = tid >> 4;
    float tr[16];
#pragma unroll
    for (int q = 0; q < 4; q++) {
        const float4 v = *(const float4*)&sH[gT * 256 + aT * 16 + q * 4];
        tr[q * 4 + 0] = v.x; tr[q * 4 + 1] = v.y; tr[q * 4 + 2] = v.z; tr[q * 4 + 3] = v.w;
    }
    __syncthreads();   // sH (=T) now free for Tf chunk buffer

    // ---- Tf chunks (16 c's each) fused with conv GEMM ----
    const int oc  = (tid & 31) << 2;   // 4 consecutive output channels
    const int gsv = tid >> 5;          // groups {gsv, gsv+8}
    float4 ca0 = make_float4(0.f, 0.f, 0.f, 0.f);
    float4 ca1 = make_float4(0.f, 0.f, 0.f, 0.f);

#pragma unroll 1
    for (int cb = 0; cb < 5; ++cb) {
        // compute Tf[gT][aT][c] for c in [cb*16, cb*16+16) -> sH[g][cl*16 + a]
#pragma unroll
        for (int q = 0; q < 4; q++) {
            const int c0 = cb * 16 + q * 4;
            float sx = 0.f, sy = 0.f, sz = 0.f, sw2 = 0.f;
#pragma unroll
            for (int k = 0; k < 16; k++) {
                const float4 f = *(const float4*)&sF[gT * 1288 + k * 80 + c0];
                sx = fmaf(tr[k], f.x, sx); sy = fmaf(tr[k], f.y, sy);
                sz = fmaf(tr[k], f.z, sz); sw2 = fmaf(tr[k], f.w, sw2);
            }
            sH[gT * 256 + (q * 4 + 0) * 16 + aT] = sx;
            sH[gT * 256 + (q * 4 + 1) * 16 + aT] = sy;
            sH[gT * 256 + (q * 4 + 2) * 16 + aT] = sz;
            sH[gT * 256 + (q * 4 + 3) * 16 + aT] = sw2;
        }
        __syncthreads();

        // conv partial: j local in [0,256), global j = cb*256 + j = c*16 + a
        const float* wt = g_wt + (size_t)cb * 256 * 128;
#pragma unroll 4
        for (int j4 = 0; j4 < 64; ++j4) {
            const float4 h0 = *(const float4*)&sH[gsv * 256 + j4 * 4];
            const float4 h1 = *(const float4*)&sH[(gsv + 8) * 256 + j4 * 4];
            const float4 w0 = __ldg((const float4*)&wt[(j4 * 4 + 0) * 128 + oc]);
            const float4 w1 = __ldg((const float4*)&wt[(j4 * 4 + 1) * 128 + oc]);
            const float4 w2 = __ldg((const float4*)&wt[(j4 * 4 + 2) * 128 + oc]);
            const float4 w3 = __ldg((const float4*)&wt[(j4 * 4 + 3) * 128 + oc]);
            ca0.x = fmaf(h0.x, w0.x, ca0.x); ca0.x = fmaf(h0.y, w1.x, ca0.x);
            ca0.x = fmaf(h0.z, w2.x, ca0.x); ca0.x = fmaf(h0.w, w3.x, ca0.x);
            ca0.y = fmaf(h0.x, w0.y, ca0.y); ca0.y = fmaf(h0.y, w1.y, ca0.y);
            ca0.y = fmaf(h0.z, w2.y, ca0.y); ca0.y = fmaf(h0.w, w3.y, ca0.y);
            ca0.z = fmaf(h0.x, w0.z, ca0.z); ca0.z = fmaf(h0.y, w1.z, ca0.z);
            ca0.z = fmaf(h0.z, w2.z, ca0.z); ca0.z = fmaf(h0.w, w3.z, ca0.z);
            ca0.w = fmaf(h0.x, w0.w, ca0.w); ca0.w = fmaf(h0.y, w1.w, ca0.w);
            ca0.w = fmaf(h0.z, w2.w, ca0.w); ca0.w = fmaf(h0.w, w3.w, ca0.w);
            ca1.x = fmaf(h1.x, w0.x, ca1.x); ca1.x = fmaf(h1.y, w1.x, ca1.x);
            ca1.x = fmaf(h1.z, w2.x, ca1.x); ca1.x = fmaf(h1.w, w3.x, ca1.x);
            ca1.y = fmaf(h1.x, w0.y, ca1.y); ca1.y = fmaf(h1.y, w1.y, ca1.y);
            ca1.y = fmaf(h1.z, w2.y, ca1.y); ca1.y = fmaf(h1.w, w3.y, ca1.y);
            ca1.z = fmaf(h1.x, w0.z, ca1.z); ca1.z = fmaf(h1.y, w1.z, ca1.z);
            ca1.z = fmaf(h1.z, w2.z, ca1.z); ca1.z = fmaf(h1.w, w3.z, ca1.z);
            ca1.w = fmaf(h1.x, w0.w, ca1.w); ca1.w = fmaf(h1.y, w1.w, ca1.w);
            ca1.w = fmaf(h1.z, w2.w, ca1.w); ca1.w = fmaf(h1.w, w3.w, ca1.w);
        }
        __syncthreads();   // before next chunk overwrites sH
    }

    // ---- epilogue: add conv bias, write out ----
    const float4 cb4 = __ldg((const float4*)&conv_b[oc]);
    const int gg = gg0 + gsv;
    float4 o0 = make_float4(ca0.x + cb4.x, ca0.y + cb4.y, ca0.z + cb4.z, ca0.w + cb4.w);
    float4 o1 = make_float4(ca1.x + cb4.x, ca1.y + cb4.y, ca1.z + cb4.z, ca1.w + cb4.w);
    *(float4*)&out_main[(size_t)gg * 128 + oc] = o0;
    *(float4*)&out_main[(size_t)(gg + 8) * 128 + oc] = o1;
}

// ---------------- launch ----------------
extern "C" void kernel_launch(void* const* d_in, const int* in_sizes, int n_in,
                              void* d_out, int out_size) {
    (void)in_sizes; (void)n_in; (void)out_size;
    const float* points   = (const float*)d_in[0];
    const float* features = (const float*)d_in[1];
    const float* lift_w   = (const float*)d_in[2];
    const float* lift_b   = (const float*)d_in[3];
    const float* bnl_g    = (const float*)d_in[4];
    const float* bnl_b    = (const float*)d_in[5];
    const float* t1_w     = (const float*)d_in[6];
    const float* t1_b     = (const float*)d_in[7];
    const float* bn1_g    = (const float*)d_in[8];
    const float* bn1_b    = (const float*)d_in[9];
    const float* t2_w     = (const float*)d_in[10];
    const float* t2_b     = (const float*)d_in[11];
    const float* bn2_g    = (const float*)d_in[12];
    const float* bn2_b    = (const float*)d_in[13];
    const float* t3_w     = (const float*)d_in[14];
    const float* t3_b     = (const float*)d_in[15];
    const float* bn3_g    = (const float*)d_in[16];
    const float* bn3_b    = (const float*)d_in[17];
    const float* conv_w   = (const float*)d_in[18];
    const float* conv_b   = (const float*)d_in[19];
    const int*   rep_idx  = (const int*)d_in[20];

    float* out      = (float*)d_out;
    float* out_rep  = out;                       // [B][R][3]
    float* out_main = out + BQ * RQ * 3;         // [B][R][128]

    cudaFuncSetAttribute(knn_kernel,  cudaFuncAttributeMaxDynamicSharedMemorySize, KNN_SMEM_BYTES);
    cudaFuncSetAttribute(main_kernel, cudaFuncAttributeMaxDynamicSharedMemorySize, MAIN_SMEM_BYTES);

    transpose_conv_kernel<<<640, 256>>>(conv_w);
    knn_kernel<<<dim3(64, 2), 256, KNN_SMEM_BYTES>>>(points, rep_idx);
    main_kernel<<<256, 256, MAIN_SMEM_BYTES>>>(
        points, features, lift_w, lift_b, bnl_g, bnl_b,
        t1_w, t1_b, bn1_g, bn1_b, t2_w, t2_b, bn2_g, bn2_b,
        t3_w, t3_b, bn3_g, bn3_b, conv_b, rep_idx, out_rep, out_main);
}

// round 2
// speedup vs baseline: 1.3215x; 1.3215x over previous
#include <cuda_runtime.h>
#include <cstdint>
#include <cfloat>
#include <cstddef>

#define BQ 2
#define NQ 8192
#define RQ 2048
#define KQ 16
#define COUTQ 128
#define GQ (BQ * RQ)

// ---------------- scratch (no allocations allowed) ----------------
__device__ int   g_nn[BQ * RQ * KQ];          // neighbor indices per rep point
__device__ float g_wt[1280 * COUTQ];          // conv_w transposed: Wt[j][o] = conv_w[o][j]
__device__ float g_tf[(size_t)GQ * 1280];     // Tf flattened: A[g][j], j = c*16 + k

// ---------------- kernel 1: transpose conv weights ----------------
__global__ void transpose_conv_kernel(const float* __restrict__ cw) {
    int t = blockIdx.x * 256 + threadIdx.x;
    if (t < 1280 * 128) {
        int j = t >> 7, o = t & 127;
        g_wt[t] = __ldg(&cw[o * 1280 + j]);
    }
}

// ---------------- kernel 2: kNN for representative points ----------------
// grid (64, 2): 32 reps per block, blockIdx.y = batch. 512 threads:
// thread = (rep_slot = tid>>4, chunk = tid&15), each scans 512 candidates.
// Shared threshold tau (min over the rep's 16 lanes of each lane's 17th-best,
// refreshed every 64 iters) gates insertions: any candidate with d2 > tau
// cannot be in the global top-17, so dropping it is safe.
#define KNN_SMEM_BYTES (NQ * 16 + 512 * 17 * 8)

__global__ __launch_bounds__(512, 1) void knn_kernel(
    const float* __restrict__ points, const int* __restrict__ rep_idx)
{
    extern __shared__ float4 sp[];               // [8192] x,y,z,sq
    float* md = (float*)(sp + NQ);               // [512][17]
    int*   mi = (int*)(md + 512 * 17);           // [512][17]
    const int tid = threadIdx.x;
    const int b   = blockIdx.y;
    const float* P = points + (size_t)b * NQ * 3;

    for (int i = tid; i < NQ; i += 512) {
        float x = P[i * 3 + 0], y = P[i * 3 + 1], z = P[i * 3 + 2];
        sp[i] = make_float4(x, y, z, fmaf(z, z, fmaf(y, y, x * x)));
    }
    __syncthreads();

    const int rl  = blockIdx.x * 32 + (tid >> 4);
    const int ch  = tid & 15;
    const int rpt = __ldg(&rep_idx[rl]);
    const float4 rp = sp[rpt];

    float bd[17]; int bi[17];
#pragma unroll
    for (int j = 0; j < 17; j++) { bd[j] = FLT_MAX; bi[j] = 0x7fffffff; }

    float tau = FLT_MAX;
    const int c0 = ch << 9;
    for (int t = 0; t < 512; ++t) {
        if ((t & 63) == 0) {
            // tau = min over this rep's 16 lanes of each lane's current 17th-best.
            float m = bd[16];
            m = fminf(m, __shfl_xor_sync(0xffffffffu, m, 1));
            m = fminf(m, __shfl_xor_sync(0xffffffffu, m, 2));
            m = fminf(m, __shfl_xor_sync(0xffffffffu, m, 4));
            m = fminf(m, __shfl_xor_sync(0xffffffffu, m, 8));
            tau = m;
        }
        // stagger start per chunk -> conflict-free shared banks; order-independent
        int c = c0 + ((t + ch) & 511);
        float4 q = sp[c];
        float dot = fmaf(rp.z, q.z, fmaf(rp.y, q.y, rp.x * q.x));
        float d2  = fmaf(-2.f, dot, rp.w + q.w);   // sq_r + sq_c - 2*dot
        if (d2 <= tau && (d2 < bd[16] || (d2 == bd[16] && c < bi[16]))) {
            float vd = d2; int vi = c;
#pragma unroll
            for (int j = 0; j < 17; j++) {
                bool sw = (vd < bd[j]) || (vd == bd[j] && vi < bi[j]);
                if (sw) { float td = bd[j]; int ti = bi[j];
                          bd[j] = vd; bi[j] = vi; vd = td; vi = ti; }
            }
        }
    }
#pragma unroll
    for (int j = 0; j < 17; j++) { md[tid * 17 + j] = bd[j]; mi[tid * 17 + j] = bi[j]; }
    __syncthreads();

    // merge 16 sorted lists per rep; drop rank 0 (self-rank), emit ranks 1..16
    if (tid < 32) {
        const int base = tid * 16;
        int ptr[16];
#pragma unroll
        for (int c2 = 0; c2 < 16; c2++) ptr[c2] = 0;
        const int rloc = blockIdx.x * 32 + tid;
        int* dst = &g_nn[((size_t)b * RQ + rloc) * KQ];
        for (int t = 0; t < 17; ++t) {
            float best = FLT_MAX; int bidx = 0x7fffffff; int bc = -1;
#pragma unroll
            for (int c2 = 0; c2 < 16; c2++) {
                int p = ptr[c2];
                float d = md[(base + c2) * 17 + p];
                int   i2 = mi[(base + c2) * 17 + p];
                if (d < best || (d == best && i2 < bidx)) { best = d; bidx = i2; bc = c2; }
            }
#pragma unroll
            for (int c2 = 0; c2 < 16; c2++) if (c2 == bc) ptr[c2]++;
            if (t > 0) dst[t - 1] = bidx;
        }
    }
}

// ---------------- kernel 3: gather + lift + T-net MLP + Tf, store Tf ----------------
// 256 blocks, each handles G=16 groups with 256 threads.
// Shared layout (floats):
//   sH   [16][256]     @ 0       (hidden / T / Tf chunk buffer, reused)
//   sF   [16][1288]    @ 4096    (feat: [16 k][80 c] padded stride 1288/group)
//   sP   [16][48]      @ 24704   (pf rows)
#define MAIN_SMEM_FLOATS (4096 + 16 * 1288 + 768)
#define MAIN_SMEM_BYTES  (MAIN_SMEM_FLOATS * 4)
#define SF_OFF 4096
#define SP_OFF 24704

__global__ __launch_bounds__(256, 2) void mlp_kernel(
    const float* __restrict__ points,  const float* __restrict__ features,
    const float* __restrict__ lift_w,  const float* __restrict__ lift_b,
    const float* __restrict__ bnl_g,   const float* __restrict__ bnl_b,
    const float* __restrict__ t1_w,    const float* __restrict__ t1_b,
    const float* __restrict__ bn1_g,   const float* __restrict__ bn1_b,
    const float* __restrict__ t2_w,    const float* __restrict__ t2_b,
    const float* __restrict__ bn2_g,   const float* __restrict__ bn2_b,
    const float* __restrict__ t3_w,    const float* __restrict__ t3_b,
    const float* __restrict__ bn3_g,   const float* __restrict__ bn3_b,
    const int* __restrict__ rep_idx,   float* __restrict__ out_rep)
{
    extern __shared__ float sm[];
    float* sH = sm;
    float* sF = sm + SF_OFF;
    float* sP = sm + SP_OFF;
    const int tid = threadIdx.x;
    const int gg0 = blockIdx.x * 16;

    // ---- gather + lift: thread = (group g, neighbor k) ----
    {
        const int g = tid >> 4, k = tid & 15;
        const int gg = gg0 + g;
        const int b = gg >> 11, rl = gg & 2047;
        const int rpt = __ldg(&rep_idx[rl]);
        const float* rpp = points + ((size_t)b * NQ + rpt) * 3;
        const float rx = __ldg(rpp), ry = __ldg(rpp + 1), rz = __ldg(rpp + 2);
        const int nb = g_nn[gg * KQ + k];
        const float* npp = points + ((size_t)b * NQ + nb) * 3;
        const float px = __ldg(npp) - rx, py = __ldg(npp + 1) - ry, pz = __ldg(npp + 2) - rz;
        sP[g * 48 + k * 3 + 0] = px;
        sP[g * 48 + k * 3 + 1] = py;
        sP[g * 48 + k * 3 + 2] = pz;
        if (k == 0) {
            out_rep[gg * 3 + 0] = rx; out_rep[gg * 3 + 1] = ry; out_rep[gg * 3 + 2] = rz;
        }
        // lifted features -> feat cols [0,16)
        float* fl = &sF[g * 1288 + k * 80];
#pragma unroll
        for (int j = 0; j < 16; j++) {
            float d = fmaf(pz, __ldg(&lift_w[j * 3 + 2]),
                      fmaf(py, __ldg(&lift_w[j * 3 + 1]), px * __ldg(&lift_w[j * 3 + 0])));
            float v = fmaf(d + __ldg(&lift_b[j]), __ldg(&bnl_g[j]), __ldg(&bnl_b[j]));
            fl[j] = fmaxf(v, 0.f);
        }
        // gathered neighbor features -> feat cols [16,80)
        const float4* fr = (const float4*)(features + ((size_t)b * NQ + nb) * 64);
        float4* fd = (float4*)(fl + 16);
#pragma unroll
        for (int q = 0; q < 16; q++) fd[q] = __ldg(fr + q);
    }
    __syncthreads();

    const int i = tid;   // output neuron for the three MLP GEMMs
    float acc[16];

    // ---- t1: [16 groups x 48] @ t1_w.T -> H[16][256], bn+relu ----
    {
#pragma unroll
        for (int g2 = 0; g2 < 16; g2++) acc[g2] = 0.f;
        const float4* w4 = (const float4*)(t1_w + i * 48);
#pragma unroll
        for (int jj = 0; jj < 12; ++jj) {
            const float4 w = __ldg(w4 + jj);
#pragma unroll
            for (int g2 = 0; g2 < 16; ++g2) {
                const float4 h = *(const float4*)&sP[g2 * 48 + jj * 4];
                acc[g2] = fmaf(w.x, h.x, acc[g2]); acc[g2] = fmaf(w.y, h.y, acc[g2]);
                acc[g2] = fmaf(w.z, h.z, acc[g2]); acc[g2] = fmaf(w.w, h.w, acc[g2]);
            }
        }
        const float tb = __ldg(&t1_b[i]), bg = __ldg(&bn1_g[i]), bb = __ldg(&bn1_b[i]);
#pragma unroll
        for (int g2 = 0; g2 < 16; g2++)
            sH[g2 * 256 + i] = fmaxf(fmaf(acc[g2] + tb, bg, bb), 0.f);
    }
    __syncthreads();

    // ---- t2: H @ t2_w.T, bn+relu (in-place with sync fence) ----
    {
#pragma unroll
        for (int g2 = 0; g2 < 16; g2++) acc[g2] = 0.f;
        const float4* w4 = (const float4*)(t2_w + i * 256);
#pragma unroll 4
        for (int jj = 0; jj < 64; ++jj) {
            const float4 w = __ldg(w4 + jj);
#pragma unroll
            for (int g2 = 0; g2 < 16; ++g2) {
                const float4 h = *(const float4*)&sH[g2 * 256 + jj * 4];
                acc[g2] = fmaf(w.x, h.x, acc[g2]); acc[g2] = fmaf(w.y, h.y, acc[g2]);
                acc[g2] = fmaf(w.z, h.z, acc[g2]); acc[g2] = fmaf(w.w, h.w, acc[g2]);
            }
        }
        const float tb = __ldg(&t2_b[i]), bg = __ldg(&bn2_g[i]), bb = __ldg(&bn2_b[i]);
        __syncthreads();   // all reads of sH done before overwrite
#pragma unroll
        for (int g2 = 0; g2 < 16; g2++)
            sH[g2 * 256 + i] = fmaxf(fmaf(acc[g2] + tb, bg, bb), 0.f);
    }
    __syncthreads();

    // ---- t3: H @ t3_w.T, bn (no relu) -> T[16 groups][16][16] stored in sH ----
    {
#pragma unroll
        for (int g2 = 0; g2 < 16; g2++) acc[g2] = 0.f;
        const float4* w4 = (const float4*)(t3_w + i * 256);
#pragma unroll 4
        for (int jj = 0; jj < 64; ++jj) {
            const float4 w = __ldg(w4 + jj);
#pragma unroll
            for (int g2 = 0; g2 < 16; ++g2) {
                const float4 h = *(const float4*)&sH[g2 * 256 + jj * 4];
                acc[g2] = fmaf(w.x, h.x, acc[g2]); acc[g2] = fmaf(w.y, h.y, acc[g2]);
                acc[g2] = fmaf(w.z, h.z, acc[g2]); acc[g2] = fmaf(w.w, h.w, acc[g2]);
            }
        }
        const float tb = __ldg(&t3_b[i]), bg = __ldg(&bn3_g[i]), bb = __ldg(&bn3_b[i]);
        __syncthreads();
#pragma unroll
        for (int g2 = 0; g2 < 16; g2++)
            sH[g2 * 256 + i] = fmaf(acc[g2] + tb, bg, bb);
    }
    __syncthreads();

    // ---- load per-thread T row into registers: thread = (gT, aT) ----
    const int aT = tid & 15, gT = tid >> 4;
    float tr[16];
#pragma unroll
    for (int q = 0; q < 4; q++) {
        const float4 v = *(const float4*)&sH[gT * 256 + aT * 16 + q * 4];
        tr[q * 4 + 0] = v.x; tr[q * 4 + 1] = v.y; tr[q * 4 + 2] = v.z; tr[q * 4 + 3] = v.w;
    }
    __syncthreads();   // sH (=T) now free for Tf chunk buffer

    // ---- Tf chunks (16 c's each), stored to g_tf in A[g][j=c*16+k] layout ----
    const int gw = tid >> 4;           // group for the copy phase
    const int ow = (tid & 15) * 16;    // 16-float slice within the 256-chunk
#pragma unroll 1
    for (int cb = 0; cb < 5; ++cb) {
        // compute Tf[gT][aT][c] for c in [cb*16, cb*16+16) -> sH[g][cl*16 + a]
#pragma unroll
        for (int q = 0; q < 4; q++) {
            const int c0 = cb * 16 + q * 4;
            float sx = 0.f, sy = 0.f, sz = 0.f, sw2 = 0.f;
#pragma unroll
            for (int k = 0; k < 16; k++) {
                const float4 f = *(const float4*)&sF[gT * 1288 + k * 80 + c0];
                sx = fmaf(tr[k], f.x, sx); sy = fmaf(tr[k], f.y, sy);
                sz = fmaf(tr[k], f.z, sz); sw2 = fmaf(tr[k], f.w, sw2);
            }
            sH[gT * 256 + (q * 4 + 0) * 16 + aT] = sx;
            sH[gT * 256 + (q * 4 + 1) * 16 + aT] = sy;
            sH[gT * 256 + (q * 4 + 2) * 16 + aT] = sz;
            sH[gT * 256 + (q * 4 + 3) * 16 + aT] = sw2;
        }
        __syncthreads();

        // coalesced store of the 256-float chunk per group:
        // sH[g][j_local] holds A[g][cb*256 + j_local] exactly (j = c*16 + k)
        {
            float4* dst = (float4*)&g_tf[(size_t)(gg0 + gw) * 1280 + cb * 256 + ow];
            const float4* src = (const float4*)&sH[gw * 256 + ow];
            dst[0] = src[0]; dst[1] = src[1]; dst[2] = src[2]; dst[3] = src[3];
        }
        __syncthreads();   // before next chunk overwrites sH
    }
}

// ---------------- kernel 4: conv GEMM  out[4096][128] = A[4096][1280] @ Wt[1280][128] ----------------
// grid 128 blocks: M-tile = 32 groups, full N = 128. 256 threads = (mi 0..7, ni 0..31),
// each thread computes 4 groups x 4 cols. K tiled by 160 through shared.
#define CB_KC 160
#define CONV_SMEM_BYTES ((CB_KC * 128 + 32 * 164) * 4)

__global__ __launch_bounds__(256, 1) void conv_kernel(
    const float* __restrict__ conv_b, float* __restrict__ out_main)
{
    extern __shared__ float sm[];
    float* sB = sm;                 // [160][128]
    float* sA = sm + CB_KC * 128;   // [32][164]  (row stride 164, 16B-aligned)
    const int tid = threadIdx.x;
    const int gm0 = blockIdx.x * 32;
    const int ni = tid & 31, mi = tid >> 5;

    float acc[4][4];
#pragma unroll
    for (int r = 0; r < 4; r++)
#pragma unroll
        for (int c = 0; c < 4; c++) acc[r][c] = 0.f;

#pragma unroll 1
    for (int kc = 0; kc < 1280; kc += CB_KC) {
        // load Wt tile [160][128]
#pragma unroll
        for (int q = 0; q < 20; ++q) {
            int idx = tid + q * 256;
            int j = idx >> 5, c4 = idx & 31;
            *(float4*)&sB[j * 128 + c4 * 4] =
                __ldg((const float4*)&g_wt[(size_t)(kc + j) * 128 + c4 * 4]);
        }
        // load A tile [32][160] (natural layout, coalesced)
#pragma unroll
        for (int q = 0; q < 5; ++q) {
            int idx = tid + q * 256;
            int m = idx / 40, j4 = idx % 40;
            *(float4*)&sA[m * 164 + j4 * 4] =
                __ldg((const float4*)&g_tf[(size_t)(gm0 + m) * 1280 + kc + j4 * 4]);
        }
        __syncthreads();

#pragma unroll 4
        for (int k = 0; k < CB_KC; ++k) {
            const float4 b4 = *(const float4*)&sB[k * 128 + ni * 4];
            const float a0 = sA[(mi * 4 + 0) * 164 + k];
            const float a1 = sA[(mi * 4 + 1) * 164 + k];
            const float a2 = sA[(mi * 4 + 2) * 164 + k];
            const float a3 = sA[(mi * 4 + 3) * 164 + k];
            acc[0][0] = fmaf(a0, b4.x, acc[0][0]); acc[0][1] = fmaf(a0, b4.y, acc[0][1]);
            acc[0][2] = fmaf(a0, b4.z, acc[0][2]); acc[0][3] = fmaf(a0, b4.w, acc[0][3]);
            acc[1][0] = fmaf(a1, b4.x, acc[1][0]); acc[1][1] = fmaf(a1, b4.y, acc[1][1]);
            acc[1][2] = fmaf(a1, b4.z, acc[1][2]); acc[1][3] = fmaf(a1, b4.w, acc[1][3]);
            acc[2][0] = fmaf(a2, b4.x, acc[2][0]); acc[2][1] = fmaf(a2, b4.y, acc[2][1]);
            acc[2][2] = fmaf(a2, b4.z, acc[2][2]); acc[2][3] = fmaf(a2, b4.w, acc[2][3]);
            acc[3][0] = fmaf(a3, b4.x, acc[3][0]); acc[3][1] = fmaf(a3, b4.y, acc[3][1]);
            acc[3][2] = fmaf(a3, b4.z, acc[3][2]); acc[3][3] = fmaf(a3, b4.w, acc[3][3]);
        }
        __syncthreads();
    }

    const float4 cb4 = __ldg((const float4*)&conv_b[ni * 4]);
#pragma unroll
    for (int r = 0; r < 4; r++) {
        float4 o = make_float4(acc[r][0] + cb4.x, acc[r][1] + cb4.y,
                               acc[r][2] + cb4.z, acc[r][3] + cb4.w);
        *(float4*)&out_main[(size_t)(gm0 + mi * 4 + r) * 128 + ni * 4] = o;
    }
}

// ---------------- launch ----------------
extern "C" void kernel_launch(void* const* d_in, const int* in_sizes, int n_in,
                              void* d_out, int out_size) {
    (void)in_sizes; (void)n_in; (void)out_size;
    const float* points   = (const float*)d_in[0];
    const float* features = (const float*)d_in[1];
    const float* lift_w   = (const float*)d_in[2];
    const float* lift_b   = (const float*)d_in[3];
    const float* bnl_g    = (const float*)d_in[4];
    const float* bnl_b    = (const float*)d_in[5];
    const float* t1_w     = (const float*)d_in[6];
    const float* t1_b     = (const float*)d_in[7];
    const float* bn1_g    = (const float*)d_in[8];
    const float* bn1_b    = (const float*)d_in[9];
    const float* t2_w     = (const float*)d_in[10];
    const float* t2_b     = (const float*)d_in[11];
    const float* bn2_g    = (const float*)d_in[12];
    const float* bn2_b    = (const float*)d_in[13];
    const float* t3_w     = (const float*)d_in[14];
    const float* t3_b     = (const float*)d_in[15];
    const float* bn3_g    = (const float*)d_in[16];
    const float* bn3_b    = (const float*)d_in[17];
    const float* conv_w   = (const float*)d_in[18];
    const float* conv_b   = (const float*)d_in[19];
    const int*   rep_idx  = (const int*)d_in[20];

    float* out      = (float*)d_out;
    float* out_rep  = out;                       // [B][R][3]
    float* out_main = out + BQ * RQ * 3;         // [B][R][128]

    cudaFuncSetAttribute(knn_kernel,  cudaFuncAttributeMaxDynamicSharedMemorySize, KNN_SMEM_BYTES);
    cudaFuncSetAttribute(mlp_kernel,  cudaFuncAttributeMaxDynamicSharedMemorySize, MAIN_SMEM_BYTES);
    cudaFuncSetAttribute(conv_kernel, cudaFuncAttributeMaxDynamicSharedMemorySize, CONV_SMEM_BYTES);

    transpose_conv_kernel<<<640, 256>>>(conv_w);
    knn_kernel<<<dim3(64, 2), 512, KNN_SMEM_BYTES>>>(points, rep_idx);
    mlp_kernel<<<256, 256, MAIN_SMEM_BYTES>>>(
        points, features, lift_w, lift_b, bnl_g, bnl_b,
        t1_w, t1_b, bn1_g, bn1_b, t2_w, t2_b, bn2_g, bn2_b,
        t3_w, t3_b, bn3_g, bn3_b, rep_idx, out_rep);
    conv_kernel<<<128, 256, CONV_SMEM_BYTES>>>(conv_b, out_main);
}

// round 3
// speedup vs baseline: 2.9762x; 2.2521x over previous
#include <cuda_runtime.h>
#include <cstdint>
#include <cfloat>
#include <cstddef>

#define BQ 2
#define NQ 8192
#define RQ 2048
#define KQ 16
#define COUTQ 128
#define GQ (BQ * RQ)

// ---------------- scratch (no allocations allowed) ----------------
__device__ int    g_nn[BQ * RQ * KQ];          // neighbor indices per rep point
__device__ float  g_wt[1280 * COUTQ];          // conv_w transposed: Wt[j][o]
__device__ float  g_w1t[48 * 256];             // t1_w transposed: [k][i]
__device__ float  g_w2t[256 * 256];            // t2_w transposed: [k][i]
__device__ float  g_w3t[256 * 256];            // t3_w transposed: [k][i]
__device__ float4 g_pts4[BQ * NQ];             // (x, y, z, sq)
__device__ float  g_tf[(size_t)GQ * 1280];     // Tf flattened: A[g][j], j = c*16 + k

// ---------------- kernel 1: prep (transposes + point packing) ----------------
// index ranges: [0,163840) wt | [163840,180224) pts4 | [180224,192512) w1t |
//               [192512,258048) w2t | [258048,323584) w3t
#define PREP_TOTAL 323584

__global__ void prep_kernel(const float* __restrict__ points,
                            const float* __restrict__ t1_w,
                            const float* __restrict__ t2_w,
                            const float* __restrict__ t3_w,
                            const float* __restrict__ conv_w) {
    int e = blockIdx.x * 256 + threadIdx.x;
    if (e < 163840) {
        int j = e >> 7, o = e & 127;
        g_wt[e] = __ldg(&conv_w[o * 1280 + j]);
    } else if (e < 180224) {
        int p = e - 163840;                       // b*NQ + n
        const float* pp = points + (size_t)p * 3;
        float x = __ldg(pp), y = __ldg(pp + 1), z = __ldg(pp + 2);
        g_pts4[p] = make_float4(x, y, z, fmaf(z, z, fmaf(y, y, x * x)));
    } else if (e < 192512) {
        int p = e - 180224; int k = p >> 8, i = p & 255;
        g_w1t[p] = __ldg(&t1_w[i * 48 + k]);
    } else if (e < 258048) {
        int p = e - 192512; int k = p >> 8, i = p & 255;
        g_w2t[p] = __ldg(&t2_w[i * 256 + k]);
    } else if (e < PREP_TOTAL) {
        int p = e - 258048; int k = p >> 8, i = p & 255;
        g_w3t[p] = __ldg(&t3_w[i * 256 + k]);
    }
}

// ---------------- kernel 2: kNN, warp-per-rep filter + flush ----------------
// grid (128, 2), 512 threads = 16 warps; warp w owns rep blockIdx.x*16 + w.
// Shared per warp: 64 u64 slots. [0..16] = current sorted top-17, [17..63] = FIFO.
// Key = (order-preserving u32 of d2) << 32 | candidate index -> lexicographic
// (d2 asc, idx asc) == reference's stable top_k order. All real keys unique.

__device__ __forceinline__ unsigned long long knn_pad(int s) {
    return 0xFFFFFFFF00000000ull | (unsigned)(0x40000000 + s);
}

// warp-parallel rank sort of the 64 slots; afterwards slots[0..16] = 17 smallest
// (sorted), slots[17..63] reset to unique pads.
__device__ __forceinline__ void knn_flush(unsigned long long* S, int lane) {
    __syncwarp();
    unsigned long long k0 = S[lane], k1 = S[lane + 32];
    int r0 = 0, r1 = 0;
#pragma unroll
    for (int j = 0; j < 64; ++j) {
        unsigned long long kj = S[j];
        r0 += (kj < k0); r1 += (kj < k1);
    }
    __syncwarp();
    S[r0] = k0; S[r1] = k1;       // ranks form a permutation (keys unique)
    __syncwarp();
    S[17 + lane] = knn_pad(17 + lane);             // 17..48
    if (lane < 15) S[49 + lane] = knn_pad(49 + lane);  // 49..63
    __syncwarp();
}

__global__ __launch_bounds__(512, 2) void knn_kernel(const int* __restrict__ rep_idx) {
    __shared__ unsigned long long slots[16][64];
    const int tid = threadIdx.x;
    const int w = tid >> 5, lane = tid & 31;
    const int b = blockIdx.y;
    const int r = blockIdx.x * 16 + w;

    const int rpt = __ldg(&rep_idx[r]);
    const float4* P = g_pts4 + (size_t)b * NQ;
    const float4 rp = __ldg(&P[rpt]);

    unsigned long long* S = slots[w];
    S[lane] = knn_pad(lane);
    S[lane + 32] = knn_pad(lane + 32);
    __syncwarp();

    int cnt = 17;
    unsigned long long tau = 0xFFFFFFFFFFFFFFFFull;

#pragma unroll 1
    for (int it = 0; it < 256; ++it) {
        const int c = (it << 5) + lane;
        const float4 q = __ldg(&P[c]);
        const float dot = fmaf(rp.z, q.z, fmaf(rp.y, q.y, rp.x * q.x));
        const float d2  = fmaf(-2.f, dot, rp.w + q.w);
        const unsigned s = __float_as_uint(d2);
        const unsigned u = (s & 0x80000000u) ? ~s : (s | 0x80000000u);
        const unsigned long long key = ((unsigned long long)u << 32) | (unsigned)c;
        const bool pred = key < tau;
        const unsigned bal = __ballot_sync(0xffffffffu, pred);
        const int n = __popc(bal);
        if (cnt + n > 64) {                 // uniform branch (cnt, n uniform)
            knn_flush(S, lane);
            cnt = 17;
            tau = S[16];
        }
        if (pred) S[cnt + __popc(bal & ((1u << lane) - 1u))] = key;
        cnt += n;
    }
    if (cnt > 17) knn_flush(S, lane);

    // ranks 1..16 (rank 0 dropped, mirroring reference's idx[:, :, 1:])
    if (lane < 16)
        g_nn[((size_t)b * RQ + r) * KQ + lane] =
            (int)(unsigned)(S[lane + 1] & 0xFFFFFFFFull);
}

// ---------------- kernel 3: gather + lift + T-net MLP + Tf, store Tf ----------------
// 256 blocks, each handles 16 groups with 256 threads. Weights read via the
// transposed [k][i] copies -> lane-consecutive coalesced LDG.32.
#define MAIN_SMEM_FLOATS (4096 + 16 * 1288 + 768)
#define MAIN_SMEM_BYTES  (MAIN_SMEM_FLOATS * 4)
#define SF_OFF 4096
#define SP_OFF 24704

__global__ __launch_bounds__(256, 2) void mlp_kernel(
    const float* __restrict__ points,  const float* __restrict__ features,
    const float* __restrict__ lift_w,  const float* __restrict__ lift_b,
    const float* __restrict__ bnl_g,   const float* __restrict__ bnl_b,
    const float* __restrict__ t1_b,    const float* __restrict__ bn1_g,
    const float* __restrict__ bn1_b,   const float* __restrict__ t2_b,
    const float* __restrict__ bn2_g,   const float* __restrict__ bn2_b,
    const float* __restrict__ t3_b,    const float* __restrict__ bn3_g,
    const float* __restrict__ bn3_b,   const int* __restrict__ rep_idx,
    float* __restrict__ out_rep)
{
    extern __shared__ float sm[];
    float* sH = sm;
    float* sF = sm + SF_OFF;
    float* sP = sm + SP_OFF;
    const int tid = threadIdx.x;
    const int gg0 = blockIdx.x * 16;

    // ---- gather + lift: thread = (group g, neighbor k) ----
    {
        const int g = tid >> 4, k = tid & 15;
        const int gg = gg0 + g;
        const int b = gg >> 11, rl = gg & 2047;
        const int rpt = __ldg(&rep_idx[rl]);
        const float* rpp = points + ((size_t)b * NQ + rpt) * 3;
        const float rx = __ldg(rpp), ry = __ldg(rpp + 1), rz = __ldg(rpp + 2);
        const int nb = g_nn[gg * KQ + k];
        const float* npp = points + ((size_t)b * NQ + nb) * 3;
        const float px = __ldg(npp) - rx, py = __ldg(npp + 1) - ry, pz = __ldg(npp + 2) - rz;
        sP[g * 48 + k * 3 + 0] = px;
        sP[g * 48 + k * 3 + 1] = py;
        sP[g * 48 + k * 3 + 2] = pz;
        if (k == 0) {
            out_rep[gg * 3 + 0] = rx; out_rep[gg * 3 + 1] = ry; out_rep[gg * 3 + 2] = rz;
        }
        float* fl = &sF[g * 1288 + k * 80];
#pragma unroll
        for (int j = 0; j < 16; j++) {
            float d = fmaf(pz, __ldg(&lift_w[j * 3 + 2]),
                      fmaf(py, __ldg(&lift_w[j * 3 + 1]), px * __ldg(&lift_w[j * 3 + 0])));
            float v = fmaf(d + __ldg(&lift_b[j]), __ldg(&bnl_g[j]), __ldg(&bnl_b[j]));
            fl[j] = fmaxf(v, 0.f);
        }
        const float4* fr = (const float4*)(features + ((size_t)b * NQ + nb) * 64);
        float4* fd = (float4*)(fl + 16);
#pragma unroll
        for (int q = 0; q < 16; q++) fd[q] = __ldg(fr + q);
    }
    __syncthreads();

    const int i = tid;
    float acc[16];

    // ---- t1: pf[16][48] @ W1^T -> H[16][256], bn+relu ----
    {
#pragma unroll
        for (int g2 = 0; g2 < 16; g2++) acc[g2] = 0.f;
#pragma unroll
        for (int jj = 0; jj < 12; ++jj) {
            const float w0 = __ldg(&g_w1t[(jj * 4 + 0) * 256 + i]);
            const float w1 = __ldg(&g_w1t[(jj * 4 + 1) * 256 + i]);
            const float w2 = __ldg(&g_w1t[(jj * 4 + 2) * 256 + i]);
            const float w3 = __ldg(&g_w1t[(jj * 4 + 3) * 256 + i]);
#pragma unroll
            for (int g2 = 0; g2 < 16; ++g2) {
                const float4 h = *(const float4*)&sP[g2 * 48 + jj * 4];
                acc[g2] = fmaf(w0, h.x, acc[g2]); acc[g2] = fmaf(w1, h.y, acc[g2]);
                acc[g2] = fmaf(w2, h.z, acc[g2]); acc[g2] = fmaf(w3, h.w, acc[g2]);
            }
        }
        const float tb = __ldg(&t1_b[i]), bg = __ldg(&bn1_g[i]), bb = __ldg(&bn1_b[i]);
#pragma unroll
        for (int g2 = 0; g2 < 16; g2++)
            sH[g2 * 256 + i] = fmaxf(fmaf(acc[g2] + tb, bg, bb), 0.f);
    }
    __syncthreads();

    // ---- t2: H @ W2^T, bn+relu ----
    {
#pragma unroll
        for (int g2 = 0; g2 < 16; g2++) acc[g2] = 0.f;
#pragma unroll 4
        for (int jj = 0; jj < 64; ++jj) {
            const float w0 = __ldg(&g_w2t[(jj * 4 + 0) * 256 + i]);
            const float w1 = __ldg(&g_w2t[(jj * 4 + 1) * 256 + i]);
            const float w2 = __ldg(&g_w2t[(jj * 4 + 2) * 256 + i]);
            const float w3 = __ldg(&g_w2t[(jj * 4 + 3) * 256 + i]);
#pragma unroll
            for (int g2 = 0; g2 < 16; ++g2) {
                const float4 h = *(const float4*)&sH[g2 * 256 + jj * 4];
                acc[g2] = fmaf(w0, h.x, acc[g2]); acc[g2] = fmaf(w1, h.y, acc[g2]);
                acc[g2] = fmaf(w2, h.z, acc[g2]); acc[g2] = fmaf(w3, h.w, acc[g2]);
            }
        }
        const float tb = __ldg(&t2_b[i]), bg = __ldg(&bn2_g[i]), bb = __ldg(&bn2_b[i]);
        __syncthreads();
#pragma unroll
        for (int g2 = 0; g2 < 16; g2++)
            sH[g2 * 256 + i] = fmaxf(fmaf(acc[g2] + tb, bg, bb), 0.f);
    }
    __syncthreads();

    // ---- t3: H @ W3^T, bn (no relu) -> T[16][16][16] in sH ----
    {
#pragma unroll
        for (int g2 = 0; g2 < 16; g2++) acc[g2] = 0.f;
#pragma unroll 4
        for (int jj = 0; jj < 64; ++jj) {
            const float w0 = __ldg(&g_w3t[(jj * 4 + 0) * 256 + i]);
            const float w1 = __ldg(&g_w3t[(jj * 4 + 1) * 256 + i]);
            const float w2 = __ldg(&g_w3t[(jj * 4 + 2) * 256 + i]);
            const float w3 = __ldg(&g_w3t[(jj * 4 + 3) * 256 + i]);
#pragma unroll
            for (int g2 = 0; g2 < 16; ++g2) {
                const float4 h = *(const float4*)&sH[g2 * 256 + jj * 4];
                acc[g2] = fmaf(w0, h.x, acc[g2]); acc[g2] = fmaf(w1, h.y, acc[g2]);
                acc[g2] = fmaf(w2, h.z, acc[g2]); acc[g2] = fmaf(w3, h.w, acc[g2]);
            }
        }
        const float tb = __ldg(&t3_b[i]), bg = __ldg(&bn3_g[i]), bb = __ldg(&bn3_b[i]);
        __syncthreads();
#pragma unroll
        for (int g2 = 0; g2 < 16; g2++)
            sH[g2 * 256 + i] = fmaf(acc[g2] + tb, bg, bb);
    }
    __syncthreads();

    // ---- per-thread T row into registers: thread = (gT, aT) ----
    const int aT = tid & 15, gT = tid >> 4;
    float tr[16];
#pragma unroll
    for (int q = 0; q < 4; q++) {
        const float4 v = *(const float4*)&sH[gT * 256 + aT * 16 + q * 4];
        tr[q * 4 + 0] = v.x; tr[q * 4 + 1] = v.y; tr[q * 4 + 2] = v.z; tr[q * 4 + 3] = v.w;
    }
    __syncthreads();

    // ---- Tf chunks (16 c's each), stored to g_tf in A[g][j=c*16+k] layout ----
    const int gw = tid >> 4;
    const int ow = (tid & 15) * 16;
#pragma unroll 1
    for (int cb = 0; cb < 5; ++cb) {
#pragma unroll
        for (int q = 0; q < 4; q++) {
            const int c0 = cb * 16 + q * 4;
            float sx = 0.f, sy = 0.f, sz = 0.f, sw2 = 0.f;
#pragma unroll
            for (int k = 0; k < 16; k++) {
                const float4 f = *(const float4*)&sF[gT * 1288 + k * 80 + c0];
                sx = fmaf(tr[k], f.x, sx); sy = fmaf(tr[k], f.y, sy);
                sz = fmaf(tr[k], f.z, sz); sw2 = fmaf(tr[k], f.w, sw2);
            }
            sH[gT * 256 + (q * 4 + 0) * 16 + aT] = sx;
            sH[gT * 256 + (q * 4 + 1) * 16 + aT] = sy;
            sH[gT * 256 + (q * 4 + 2) * 16 + aT] = sz;
            sH[gT * 256 + (q * 4 + 3) * 16 + aT] = sw2;
        }
        __syncthreads();
        {
            float4* dst = (float4*)&g_tf[(size_t)(gg0 + gw) * 1280 + cb * 256 + ow];
            const float4* src = (const float4*)&sH[gw * 256 + ow];
            dst[0] = src[0]; dst[1] = src[1]; dst[2] = src[2]; dst[3] = src[3];
        }
        __syncthreads();
    }
}

// ---------------- kernel 4: conv GEMM  out[4096][128] = A[4096][1280] @ Wt[1280][128] ----------------
// 256 blocks, M-tile 16, N=128, 256 threads = (mi 0..7 -> 2 rows, ni 0..31 -> 4 cols).
#define CV_KC 128
#define CONV_SMEM_BYTES ((CV_KC * 128 + 16 * 132) * 4)

__global__ __launch_bounds__(256, 2) void conv_kernel(
    const float* __restrict__ conv_b, float* __restrict__ out_main)
{
    extern __shared__ float sm[];
    float* sB = sm;                  // [128][128]
    float* sA = sm + CV_KC * 128;    // [16][132]
    const int tid = threadIdx.x;
    const int gm0 = blockIdx.x * 16;
    const int ni = tid & 31, mi = tid >> 5;
    const int row0 = mi * 2;

    float acc[2][4];
#pragma unroll
    for (int r = 0; r < 2; r++)
#pragma unroll
        for (int c = 0; c < 4; c++) acc[r][c] = 0.f;

#pragma unroll 1
    for (int kc = 0; kc < 1280; kc += CV_KC) {
        const float4* srcB = (const float4*)&g_wt[(size_t)kc * 128];
        float4* dstB = (float4*)sB;
#pragma unroll
        for (int q = 0; q < 16; ++q)
            dstB[tid + q * 256] = __ldg(&srcB[tid + q * 256]);
#pragma unroll
        for (int q = 0; q < 2; ++q) {
            int idx = tid + q * 256;
            int m = idx >> 5, j4 = idx & 31;
            *(float4*)&sA[m * 132 + j4 * 4] =
                __ldg((const float4*)&g_tf[(size_t)(gm0 + m) * 1280 + kc + j4 * 4]);
        }
        __syncthreads();

#pragma unroll 4
        for (int k = 0; k < CV_KC; k += 2) {
            const float4 b0 = *(const float4*)&sB[k * 128 + ni * 4];
            const float4 b1 = *(const float4*)&sB[(k + 1) * 128 + ni * 4];
            const float2 a0 = *(const float2*)&sA[(row0 + 0) * 132 + k];
            const float2 a1 = *(const float2*)&sA[(row0 + 1) * 132 + k];
            acc[0][0] = fmaf(a0.x, b0.x, acc[0][0]); acc[0][1] = fmaf(a0.x, b0.y, acc[0][1]);
            acc[0][2] = fmaf(a0.x, b0.z, acc[0][2]); acc[0][3] = fmaf(a0.x, b0.w, acc[0][3]);
            acc[1][0] = fmaf(a1.x, b0.x, acc[1][0]); acc[1][1] = fmaf(a1.x, b0.y, acc[1][1]);
            acc[1][2] = fmaf(a1.x, b0.z, acc[1][2]); acc[1][3] = fmaf(a1.x, b0.w, acc[1][3]);
            acc[0][0] = fmaf(a0.y, b1.x, acc[0][0]); acc[0][1] = fmaf(a0.y, b1.y, acc[0][1]);
            acc[0][2] = fmaf(a0.y, b1.z, acc[0][2]); acc[0][3] = fmaf(a0.y, b1.w, acc[0][3]);
            acc[1][0] = fmaf(a1.y, b1.x, acc[1][0]); acc[1][1] = fmaf(a1.y, b1.y, acc[1][1]);
            acc[1][2] = fmaf(a1.y, b1.z, acc[1][2]); acc[1][3] = fmaf(a1.y, b1.w, acc[1][3]);
        }
        __syncthreads();
    }

    const float4 cb4 = __ldg((const float4*)&conv_b[ni * 4]);
#pragma unroll
    for (int r = 0; r < 2; r++) {
        float4 o = make_float4(acc[r][0] + cb4.x, acc[r][1] + cb4.y,
                               acc[r][2] + cb4.z, acc[r][3] + cb4.w);
        *(float4*)&out_main[(size_t)(gm0 + row0 + r) * 128 + ni * 4] = o;
    }
}

// ---------------- launch ----------------
extern "C" void kernel_launch(void* const* d_in, const int* in_sizes, int n_in,
                              void* d_out, int out_size) {
    (void)in_sizes; (void)n_in; (void)out_size;
    const float* points   = (const float*)d_in[0];
    const float* features = (const float*)d_in[1];
    const float* lift_w   = (const float*)d_in[2];
    const float* lift_b   = (const float*)d_in[3];
    const float* bnl_g    = (const float*)d_in[4];
    const float* bnl_b    = (const float*)d_in[5];
    const float* t1_w     = (const float*)d_in[6];
    const float* t1_b     = (const float*)d_in[7];
    const float* bn1_g    = (const float*)d_in[8];
    const float* bn1_b    = (const float*)d_in[9];
    const float* t2_w     = (const float*)d_in[10];
    const float* t2_b     = (const float*)d_in[11];
    const float* bn2_g    = (const float*)d_in[12];
    const float* bn2_b    = (const float*)d_in[13];
    const float* t3_w     = (const float*)d_in[14];
    const float* t3_b     = (const float*)d_in[15];
    const float* bn3_g    = (const float*)d_in[16];
    const float* bn3_b    = (const float*)d_in[17];
    const float* conv_w   = (const float*)d_in[18];
    const float* conv_b   = (const float*)d_in[19];
    const int*   rep_idx  = (const int*)d_in[20];

    float* out      = (float*)d_out;
    float* out_rep  = out;                       // [B][R][3]
    float* out_main = out + BQ * RQ * 3;         // [B][R][128]

    cudaFuncSetAttribute(mlp_kernel,  cudaFuncAttributeMaxDynamicSharedMemorySize, MAIN_SMEM_BYTES);
    cudaFuncSetAttribute(conv_kernel, cudaFuncAttributeMaxDynamicSharedMemorySize, CONV_SMEM_BYTES);

    prep_kernel<<<(PREP_TOTAL + 255) / 256, 256>>>(points, t1_w, t2_w, t3_w, conv_w);
    knn_kernel<<<dim3(128, 2), 512>>>(rep_idx);
    mlp_kernel<<<256, 256, MAIN_SMEM_BYTES>>>(
        points, features, lift_w, lift_b, bnl_g, bnl_b,
        t1_b, bn1_g, bn1_b, t2_b, bn2_g, bn2_b,
        t3_b, bn3_g, bn3_b, rep_idx, out_rep);
    conv_kernel<<<256, 256, CONV_SMEM_BYTES>>>(conv_b, out_main);
}

// round 4
// speedup vs baseline: 3.2952x; 1.1072x over previous
#include <cuda_runtime.h>
#include <cstdint>
#include <cfloat>
#include <cstddef>

#define BQ 2
#define NQ 8192
#define RQ 2048
#define KQ 16
#define COUTQ 128
#define GQ (BQ * RQ)

// ---------------- scratch (no allocations allowed) ----------------
__device__ int    g_nn[BQ * RQ * KQ];          // neighbor indices per rep point
__device__ float  g_wt[1280 * COUTQ];          // conv_w transposed: Wt[j][o]
__device__ float  g_w1t[48 * 256];             // t1_w transposed: [k][i]
__device__ float  g_w2t[256 * 256];            // t2_w transposed: [k][i]
__device__ float  g_w3t[256 * 256];            // t3_w transposed: [k][i]
__device__ float4 g_pts4[BQ * NQ];             // (x, y, z, sq)
__device__ float  g_tf[(size_t)GQ * 1280];     // Tf flattened: A[g][j], j = c*16 + k
__device__ float  g_part[4][(size_t)GQ * COUTQ]; // split-K partials

// ---------------- kernel 1: prep (transposes + point packing) ----------------
#define PREP_TOTAL 323584

__global__ void prep_kernel(const float* __restrict__ points,
                            const float* __restrict__ t1_w,
                            const float* __restrict__ t2_w,
                            const float* __restrict__ t3_w,
                            const float* __restrict__ conv_w) {
    int e = blockIdx.x * 256 + threadIdx.x;
    if (e < 163840) {
        int j = e >> 7, o = e & 127;
        g_wt[e] = __ldg(&conv_w[o * 1280 + j]);
    } else if (e < 180224) {
        int p = e - 163840;                       // b*NQ + n
        const float* pp = points + (size_t)p * 3;
        float x = __ldg(pp), y = __ldg(pp + 1), z = __ldg(pp + 2);
        g_pts4[p] = make_float4(x, y, z, fmaf(z, z, fmaf(y, y, x * x)));
    } else if (e < 192512) {
        int p = e - 180224; int k = p >> 8, i = p & 255;
        g_w1t[p] = __ldg(&t1_w[i * 48 + k]);
    } else if (e < 258048) {
        int p = e - 192512; int k = p >> 8, i = p & 255;
        g_w2t[p] = __ldg(&t2_w[i * 256 + k]);
    } else if (e < PREP_TOTAL) {
        int p = e - 258048; int k = p >> 8, i = p & 255;
        g_w3t[p] = __ldg(&t3_w[i * 256 + k]);
    }
}

// ---------------- kernel 2: kNN, warp-per-rep filter + flush ----------------
__device__ __forceinline__ unsigned long long knn_pad(int s) {
    return 0xFFFFFFFF00000000ull | (unsigned)(0x40000000 + s);
}

__device__ __forceinline__ void knn_flush(unsigned long long* S, int lane) {
    __syncwarp();
    unsigned long long k0 = S[lane], k1 = S[lane + 32];
    int r0 = 0, r1 = 0;
#pragma unroll
    for (int j = 0; j < 64; ++j) {
        unsigned long long kj = S[j];
        r0 += (kj < k0); r1 += (kj < k1);
    }
    __syncwarp();
    S[r0] = k0; S[r1] = k1;       // ranks form a permutation (keys unique)
    __syncwarp();
    S[17 + lane] = knn_pad(17 + lane);
    if (lane < 15) S[49 + lane] = knn_pad(49 + lane);
    __syncwarp();
}

__global__ __launch_bounds__(512, 2) void knn_kernel(const int* __restrict__ rep_idx) {
    __shared__ unsigned long long slots[16][64];
    const int tid = threadIdx.x;
    const int w = tid >> 5, lane = tid & 31;
    const int b = blockIdx.y;
    const int r = blockIdx.x * 16 + w;

    const int rpt = __ldg(&rep_idx[r]);
    const float4* P = g_pts4 + (size_t)b * NQ;
    const float4 rp = __ldg(&P[rpt]);

    unsigned long long* S = slots[w];
    S[lane] = knn_pad(lane);
    S[lane + 32] = knn_pad(lane + 32);
    __syncwarp();

    int cnt = 17;
    unsigned long long tau = 0xFFFFFFFFFFFFFFFFull;

#pragma unroll 1
    for (int it = 0; it < 256; ++it) {
        const int c = (it << 5) + lane;
        const float4 q = __ldg(&P[c]);
        const float dot = fmaf(rp.z, q.z, fmaf(rp.y, q.y, rp.x * q.x));
        const float d2  = fmaf(-2.f, dot, rp.w + q.w);
        const unsigned s = __float_as_uint(d2);
        const unsigned u = (s & 0x80000000u) ? ~s : (s | 0x80000000u);
        const unsigned long long key = ((unsigned long long)u << 32) | (unsigned)c;
        const bool pred = key < tau;
        const unsigned bal = __ballot_sync(0xffffffffu, pred);
        const int n = __popc(bal);
        if (cnt + n > 64) {
            knn_flush(S, lane);
            cnt = 17;
            tau = S[16];
        }
        if (pred) S[cnt + __popc(bal & ((1u << lane) - 1u))] = key;
        cnt += n;
    }
    if (cnt > 17) knn_flush(S, lane);

    if (lane < 16)
        g_nn[((size_t)b * RQ + r) * KQ + lane] =
            (int)(unsigned)(S[lane + 1] & 0xFFFFFFFFull);
}

// ---------------- kernel 3: gather + lift + T-net MLP + Tf, store Tf ----------------
#define MAIN_SMEM_FLOATS (4096 + 16 * 1288 + 768)
#define MAIN_SMEM_BYTES  (MAIN_SMEM_FLOATS * 4)
#define SF_OFF 4096
#define SP_OFF 24704

__global__ __launch_bounds__(256, 2) void mlp_kernel(
    const float* __restrict__ points,  const float* __restrict__ features,
    const float* __restrict__ lift_w,  const float* __restrict__ lift_b,
    const float* __restrict__ bnl_g,   const float* __restrict__ bnl_b,
    const float* __restrict__ t1_b,    const float* __restrict__ bn1_g,
    const float* __restrict__ bn1_b,   const float* __restrict__ t2_b,
    const float* __restrict__ bn2_g,   const float* __restrict__ bn2_b,
    const float* __restrict__ t3_b,    const float* __restrict__ bn3_g,
    const float* __restrict__ bn3_b,   const int* __restrict__ rep_idx,
    float* __restrict__ out_rep)
{
    extern __shared__ float sm[];
    float* sH = sm;
    float* sF = sm + SF_OFF;
    float* sP = sm + SP_OFF;
    const int tid = threadIdx.x;
    const int gg0 = blockIdx.x * 16;

    {
        const int g = tid >> 4, k = tid & 15;
        const int gg = gg0 + g;
        const int b = gg >> 11, rl = gg & 2047;
        const int rpt = __ldg(&rep_idx[rl]);
        const float* rpp = points + ((size_t)b * NQ + rpt) * 3;
        const float rx = __ldg(rpp), ry = __ldg(rpp + 1), rz = __ldg(rpp + 2);
        const int nb = g_nn[gg * KQ + k];
        const float* npp = points + ((size_t)b * NQ + nb) * 3;
        const float px = __ldg(npp) - rx, py = __ldg(npp + 1) - ry, pz = __ldg(npp + 2) - rz;
        sP[g * 48 + k * 3 + 0] = px;
        sP[g * 48 + k * 3 + 1] = py;
        sP[g * 48 + k * 3 + 2] = pz;
        if (k == 0) {
            out_rep[gg * 3 + 0] = rx; out_rep[gg * 3 + 1] = ry; out_rep[gg * 3 + 2] = rz;
        }
        float* fl = &sF[g * 1288 + k * 80];
#pragma unroll
        for (int j = 0; j < 16; j++) {
            float d = fmaf(pz, __ldg(&lift_w[j * 3 + 2]),
                      fmaf(py, __ldg(&lift_w[j * 3 + 1]), px * __ldg(&lift_w[j * 3 + 0])));
            float v = fmaf(d + __ldg(&lift_b[j]), __ldg(&bnl_g[j]), __ldg(&bnl_b[j]));
            fl[j] = fmaxf(v, 0.f);
        }
        const float4* fr = (const float4*)(features + ((size_t)b * NQ + nb) * 64);
        float4* fd = (float4*)(fl + 16);
#pragma unroll
        for (int q = 0; q < 16; q++) fd[q] = __ldg(fr + q);
    }
    __syncthreads();

    const int i = tid;
    float acc[16];

    // ---- t1 ----
    {
#pragma unroll
        for (int g2 = 0; g2 < 16; g2++) acc[g2] = 0.f;
#pragma unroll
        for (int jj = 0; jj < 12; ++jj) {
            const float w0 = __ldg(&g_w1t[(jj * 4 + 0) * 256 + i]);
            const float w1 = __ldg(&g_w1t[(jj * 4 + 1) * 256 + i]);
            const float w2 = __ldg(&g_w1t[(jj * 4 + 2) * 256 + i]);
            const float w3 = __ldg(&g_w1t[(jj * 4 + 3) * 256 + i]);
#pragma unroll
            for (int g2 = 0; g2 < 16; ++g2) {
                const float4 h = *(const float4*)&sP[g2 * 48 + jj * 4];
                acc[g2] = fmaf(w0, h.x, acc[g2]); acc[g2] = fmaf(w1, h.y, acc[g2]);
                acc[g2] = fmaf(w2, h.z, acc[g2]); acc[g2] = fmaf(w3, h.w, acc[g2]);
            }
        }
        const float tb = __ldg(&t1_b[i]), bg = __ldg(&bn1_g[i]), bb = __ldg(&bn1_b[i]);
#pragma unroll
        for (int g2 = 0; g2 < 16; g2++)
            sH[g2 * 256 + i] = fmaxf(fmaf(acc[g2] + tb, bg, bb), 0.f);
    }
    __syncthreads();

    // ---- t2 ----
    {
#pragma unroll
        for (int g2 = 0; g2 < 16; g2++) acc[g2] = 0.f;
#pragma unroll 4
        for (int jj = 0; jj < 64; ++jj) {
            const float w0 = __ldg(&g_w2t[(jj * 4 + 0) * 256 + i]);
            const float w1 = __ldg(&g_w2t[(jj * 4 + 1) * 256 + i]);
            const float w2 = __ldg(&g_w2t[(jj * 4 + 2) * 256 + i]);
            const float w3 = __ldg(&g_w2t[(jj * 4 + 3) * 256 + i]);
#pragma unroll
            for (int g2 = 0; g2 < 16; ++g2) {
                const float4 h = *(const float4*)&sH[g2 * 256 + jj * 4];
                acc[g2] = fmaf(w0, h.x, acc[g2]); acc[g2] = fmaf(w1, h.y, acc[g2]);
                acc[g2] = fmaf(w2, h.z, acc[g2]); acc[g2] = fmaf(w3, h.w, acc[g2]);
            }
        }
        const float tb = __ldg(&t2_b[i]), bg = __ldg(&bn2_g[i]), bb = __ldg(&bn2_b[i]);
        __syncthreads();
#pragma unroll
        for (int g2 = 0; g2 < 16; g2++)
            sH[g2 * 256 + i] = fmaxf(fmaf(acc[g2] + tb, bg, bb), 0.f);
    }
    __syncthreads();

    // ---- t3 ----
    {
#pragma unroll
        for (int g2 = 0; g2 < 16; g2++) acc[g2] = 0.f;
#pragma unroll 4
        for (int jj = 0; jj < 64; ++jj) {
            const float w0 = __ldg(&g_w3t[(jj * 4 + 0) * 256 + i]);
            const float w1 = __ldg(&g_w3t[(jj * 4 + 1) * 256 + i]);
            const float w2 = __ldg(&g_w3t[(jj * 4 + 2) * 256 + i]);
            const float w3 = __ldg(&g_w3t[(jj * 4 + 3) * 256 + i]);
#pragma unroll
            for (int g2 = 0; g2 < 16; ++g2) {
                const float4 h = *(const float4*)&sH[g2 * 256 + jj * 4];
                acc[g2] = fmaf(w0, h.x, acc[g2]); acc[g2] = fmaf(w1, h.y, acc[g2]);
                acc[g2] = fmaf(w2, h.z, acc[g2]); acc[g2] = fmaf(w3, h.w, acc[g2]);
            }
        }
        const float tb = __ldg(&t3_b[i]), bg = __ldg(&bn3_g[i]), bb = __ldg(&bn3_b[i]);
        __syncthreads();
#pragma unroll
        for (int g2 = 0; g2 < 16; g2++)
            sH[g2 * 256 + i] = fmaf(acc[g2] + tb, bg, bb);
    }
    __syncthreads();

    const int aT = tid & 15, gT = tid >> 4;
    float tr[16];
#pragma unroll
    for (int q = 0; q < 4; q++) {
        const float4 v = *(const float4*)&sH[gT * 256 + aT * 16 + q * 4];
        tr[q * 4 + 0] = v.x; tr[q * 4 + 1] = v.y; tr[q * 4 + 2] = v.z; tr[q * 4 + 3] = v.w;
    }
    __syncthreads();

    const int gw = tid >> 4;
    const int ow = (tid & 15) * 16;
#pragma unroll 1
    for (int cb = 0; cb < 5; ++cb) {
#pragma unroll
        for (int q = 0; q < 4; q++) {
            const int c0 = cb * 16 + q * 4;
            float sx = 0.f, sy = 0.f, sz = 0.f, sw2 = 0.f;
#pragma unroll
            for (int k = 0; k < 16; k++) {
                const float4 f = *(const float4*)&sF[gT * 1288 + k * 80 + c0];
                sx = fmaf(tr[k], f.x, sx); sy = fmaf(tr[k], f.y, sy);
                sz = fmaf(tr[k], f.z, sz); sw2 = fmaf(tr[k], f.w, sw2);
            }
            sH[gT * 256 + (q * 4 + 0) * 16 + aT] = sx;
            sH[gT * 256 + (q * 4 + 1) * 16 + aT] = sy;
            sH[gT * 256 + (q * 4 + 2) * 16 + aT] = sz;
            sH[gT * 256 + (q * 4 + 3) * 16 + aT] = sw2;
        }
        __syncthreads();
        {
            float4* dst = (float4*)&g_tf[(size_t)(gg0 + gw) * 1280 + cb * 256 + ow];
            const float4* src = (const float4*)&sH[gw * 256 + ow];
            dst[0] = src[0]; dst[1] = src[1]; dst[2] = src[2]; dst[3] = src[3];
        }
        __syncthreads();
    }
}

// ---------------- kernel 4: conv GEMM, split-K ----------------
// out_part[kz][m][o] = sum_{k in kz-slice of 320} A[m][k] * Wt[k][o]
// grid (64, 4): blockIdx.x = M-tile (64 rows), blockIdx.y = kz.
// 128 threads, each computes 8 rows x 8 cols (64 accumulators).
#define CV_KC   32
#define CV_SA_S 33                       // sA row stride (floats), odd -> conflict-free
#define CONV_SMEM_BYTES ((64 * CV_SA_S + CV_KC * 128) * 4)

__global__ __launch_bounds__(128, 4) void conv_kernel(float* __restrict__ dummy) {
    extern __shared__ float sm[];
    float* sA = sm;                         // [64][33]   (m-major, k index inside)
    float* sB = sm + 64 * CV_SA_S;          // [32][128]
    const int tid = threadIdx.x;
    const int gm0 = blockIdx.x * 64;
    const int kz  = blockIdx.y;
    const int k0z = kz * 320;

    const int tm = (tid & 7) * 8;           // 8 rows
    const int tn = (tid >> 3) * 8;          // 8 cols

    float acc[8][8];
#pragma unroll
    for (int r = 0; r < 8; r++)
#pragma unroll
        for (int c = 0; c < 8; c++) acc[r][c] = 0.f;

#pragma unroll 1
    for (int kt = 0; kt < 320; kt += CV_KC) {
        const int kbase = k0z + kt;
        // load B tile [32][128]: 4096 floats = 1024 float4, 8 per thread
#pragma unroll
        for (int q = 0; q < 8; ++q) {
            int idx = tid + q * 128;
            int j = idx >> 5, c4 = idx & 31;
            *(float4*)&sB[j * 128 + c4 * 4] =
                __ldg((const float4*)&g_wt[(size_t)(kbase + j) * 128 + c4 * 4]);
        }
        // load A tile [64][32]: 2048 floats = 512 float4, 4 per thread (m-major)
#pragma unroll
        for (int q = 0; q < 4; ++q) {
            int idx = tid + q * 128;
            int m = idx >> 3, k4 = idx & 7;
            float4 v = __ldg((const float4*)&g_tf[(size_t)(gm0 + m) * 1280 + kbase + k4 * 4]);
            float* d = &sA[m * CV_SA_S + k4 * 4];
            d[0] = v.x; d[1] = v.y; d[2] = v.z; d[3] = v.w;
        }
        __syncthreads();

#pragma unroll 2
        for (int k = 0; k < CV_KC; ++k) {
            const float4 b0 = *(const float4*)&sB[k * 128 + tn];
            const float4 b1 = *(const float4*)&sB[k * 128 + tn + 4];
            float a[8];
#pragma unroll
            for (int r = 0; r < 8; r++) a[r] = sA[(tm + r) * CV_SA_S + k];
#pragma unroll
            for (int r = 0; r < 8; r++) {
                acc[r][0] = fmaf(a[r], b0.x, acc[r][0]);
                acc[r][1] = fmaf(a[r], b0.y, acc[r][1]);
                acc[r][2] = fmaf(a[r], b0.z, acc[r][2]);
                acc[r][3] = fmaf(a[r], b0.w, acc[r][3]);
                acc[r][4] = fmaf(a[r], b1.x, acc[r][4]);
                acc[r][5] = fmaf(a[r], b1.y, acc[r][5]);
                acc[r][6] = fmaf(a[r], b1.z, acc[r][6]);
                acc[r][7] = fmaf(a[r], b1.w, acc[r][7]);
            }
        }
        __syncthreads();
    }

    float* dst = &g_part[kz][0];
#pragma unroll
    for (int r = 0; r < 8; r++) {
        *(float4*)&dst[(size_t)(gm0 + tm + r) * 128 + tn] =
            make_float4(acc[r][0], acc[r][1], acc[r][2], acc[r][3]);
        *(float4*)&dst[(size_t)(gm0 + tm + r) * 128 + tn + 4] =
            make_float4(acc[r][4], acc[r][5], acc[r][6], acc[r][7]);
    }
    (void)dummy;
}

// ---------------- kernel 5: split-K reduce + bias ----------------
__global__ void reduce_kernel(const float* __restrict__ conv_b,
                              float* __restrict__ out_main) {
    int t = blockIdx.x * 256 + threadIdx.x;      // float4 index, 131072 total
    int o4 = (t & 31) * 4;
    const float4 p0 = *(const float4*)&g_part[0][(size_t)t * 4];
    const float4 p1 = *(const float4*)&g_part[1][(size_t)t * 4];
    const float4 p2 = *(const float4*)&g_part[2][(size_t)t * 4];
    const float4 p3 = *(const float4*)&g_part[3][(size_t)t * 4];
    const float4 cb = __ldg((const float4*)&conv_b[o4]);
    float4 o;
    o.x = ((p0.x + p1.x) + (p2.x + p3.x)) + cb.x;
    o.y = ((p0.y + p1.y) + (p2.y + p3.y)) + cb.y;
    o.z = ((p0.z + p1.z) + (p2.z + p3.z)) + cb.z;
    o.w = ((p0.w + p1.w) + (p2.w + p3.w)) + cb.w;
    *(float4*)&out_main[(size_t)t * 4] = o;
}

// ---------------- launch ----------------
extern "C" void kernel_launch(void* const* d_in, const int* in_sizes, int n_in,
                              void* d_out, int out_size) {
    (void)in_sizes; (void)n_in; (void)out_size;
    const float* points   = (const float*)d_in[0];
    const float* features = (const float*)d_in[1];
    const float* lift_w   = (const float*)d_in[2];
    const float* lift_b   = (const float*)d_in[3];
    const float* bnl_g    = (const float*)d_in[4];
    const float* bnl_b    = (const float*)d_in[5];
    const float* t1_w     = (const float*)d_in[6];
    const float* t1_b     = (const float*)d_in[7];
    const float* bn1_g    = (const float*)d_in[8];
    const float* bn1_b    = (const float*)d_in[9];
    const float* t2_w     = (const float*)d_in[10];
    const float* t2_b     = (const float*)d_in[11];
    const float* bn2_g    = (const float*)d_in[12];
    const float* bn2_b    = (const float*)d_in[13];
    const float* t3_w     = (const float*)d_in[14];
    const float* t3_b     = (const float*)d_in[15];
    const float* bn3_g    = (const float*)d_in[16];
    const float* bn3_b    = (const float*)d_in[17];
    const float* conv_w   = (const float*)d_in[18];
    const float* conv_b   = (const float*)d_in[19];
    const int*   rep_idx  = (const int*)d_in[20];

    float* out      = (float*)d_out;
    float* out_rep  = out;                       // [B][R][3]
    float* out_main = out + BQ * RQ * 3;         // [B][R][128]

    cudaFuncSetAttribute(mlp_kernel,  cudaFuncAttributeMaxDynamicSharedMemorySize, MAIN_SMEM_BYTES);
    cudaFuncSetAttribute(conv_kernel, cudaFuncAttributeMaxDynamicSharedMemorySize, CONV_SMEM_BYTES);

    prep_kernel<<<(PREP_TOTAL + 255) / 256, 256>>>(points, t1_w, t2_w, t3_w, conv_w);
    knn_kernel<<<dim3(128, 2), 512>>>(rep_idx);
    mlp_kernel<<<256, 256, MAIN_SMEM_BYTES>>>(
        points, features, lift_w, lift_b, bnl_g, bnl_b,
        t1_b, bn1_g, bn1_b, t2_b, bn2_g, bn2_b,
        t3_b, bn3_g, bn3_b, rep_idx, out_rep);
    conv_kernel<<<dim3(64, 4), 128, CONV_SMEM_BYTES>>>(nullptr);
    reduce_kernel<<<512, 256>>>(conv_b, out_main);
}

// round 5
// speedup vs baseline: 3.3818x; 1.0263x over previous
#include <cuda_runtime.h>
#include <cstdint>
#include <cfloat>
#include <cstddef>

#define BQ 2
#define NQ 8192
#define RQ 2048
#define KQ 16
#define COUTQ 128
#define GQ (BQ * RQ)

// ---------------- scratch (no allocations allowed) ----------------
__device__ int    g_nn[BQ * RQ * KQ];          // neighbor indices per rep point
__device__ float  g_wt[1280 * COUTQ];          // conv_w transposed: Wt[j][o]
__device__ float  g_w1p[12 * 1024];            // t1_w packed: [jj][i][4k]
__device__ float  g_w2p[64 * 1024];            // t2_w packed: [jj][i][4k]
__device__ float  g_w3p[64 * 1024];            // t3_w packed: [jj][i][4k]
__device__ float4 g_pts4[BQ * NQ];             // (x, y, z, sq)
__device__ float  g_tf[(size_t)GQ * 1280];     // Tf flattened: A[g][j], j = c*16 + k
__device__ float  g_part[8][(size_t)GQ * COUTQ]; // split-K partials

// ---------------- kernel 1: prep (weight packing + point packing) ----------------
// [0,163840) wt | [163840,180224) pts4 | [180224,192512) w1p |
// [192512,258048) w2p | [258048,323584) w3p
#define PREP_TOTAL 323584

__global__ void prep_kernel(const float* __restrict__ points,
                            const float* __restrict__ t1_w,
                            const float* __restrict__ t2_w,
                            const float* __restrict__ t3_w,
                            const float* __restrict__ conv_w) {
    int e = blockIdx.x * 256 + threadIdx.x;
    if (e < 163840) {
        int j = e >> 7, o = e & 127;
        g_wt[e] = __ldg(&conv_w[o * 1280 + j]);
    } else if (e < 180224) {
        int p = e - 163840;                       // b*NQ + n
        const float* pp = points + (size_t)p * 3;
        float x = __ldg(pp), y = __ldg(pp + 1), z = __ldg(pp + 2);
        g_pts4[p] = make_float4(x, y, z, fmaf(z, z, fmaf(y, y, x * x)));
    } else if (e < 192512) {
        int p = e - 180224;
        int jj = p >> 10, i = (p & 1023) >> 2, q = p & 3;
        g_w1p[p] = __ldg(&t1_w[i * 48 + jj * 4 + q]);
    } else if (e < 258048) {
        int p = e - 192512;
        int jj = p >> 10, i = (p & 1023) >> 2, q = p & 3;
        g_w2p[p] = __ldg(&t2_w[i * 256 + jj * 4 + q]);
    } else if (e < PREP_TOTAL) {
        int p = e - 258048;
        int jj = p >> 10, i = (p & 1023) >> 2, q = p & 3;
        g_w3p[p] = __ldg(&t3_w[i * 256 + jj * 4 + q]);
    }
}

// ---------------- kernel 2: kNN, warp-per-rep filter + flush ----------------
__device__ __forceinline__ unsigned long long knn_pad(int s) {
    return 0xFFFFFFFF00000000ull | (unsigned)(0x40000000 + s);
}

__device__ __forceinline__ void knn_flush(unsigned long long* S, int lane) {
    __syncwarp();
    unsigned long long k0 = S[lane], k1 = S[lane + 32];
    int r0 = 0, r1 = 0;
#pragma unroll
    for (int j = 0; j < 64; ++j) {
        unsigned long long kj = S[j];
        r0 += (kj < k0); r1 += (kj < k1);
    }
    __syncwarp();
    S[r0] = k0; S[r1] = k1;       // ranks form a permutation (keys unique)
    __syncwarp();
    S[17 + lane] = knn_pad(17 + lane);
    if (lane < 15) S[49 + lane] = knn_pad(49 + lane);
    __syncwarp();
}

__global__ __launch_bounds__(512, 2) void knn_kernel(const int* __restrict__ rep_idx) {
    __shared__ unsigned long long slots[16][64];
    const int tid = threadIdx.x;
    const int w = tid >> 5, lane = tid & 31;
    const int b = blockIdx.y;
    const int r = blockIdx.x * 16 + w;

    const int rpt = __ldg(&rep_idx[r]);
    const float4* P = g_pts4 + (size_t)b * NQ;
    const float4 rp = __ldg(&P[rpt]);

    unsigned long long* S = slots[w];
    S[lane] = knn_pad(lane);
    S[lane + 32] = knn_pad(lane + 32);
    __syncwarp();

    int cnt = 17;
    unsigned long long tau = 0xFFFFFFFFFFFFFFFFull;

#pragma unroll 1
    for (int it = 0; it < 256; ++it) {
        const int c = (it << 5) + lane;
        const float4 q = __ldg(&P[c]);
        const float dot = fmaf(rp.z, q.z, fmaf(rp.y, q.y, rp.x * q.x));
        const float d2  = fmaf(-2.f, dot, rp.w + q.w);
        const unsigned s = __float_as_uint(d2);
        const unsigned u = (s & 0x80000000u) ? ~s : (s | 0x80000000u);
        const unsigned long long key = ((unsigned long long)u << 32) | (unsigned)c;
        const bool pred = key < tau;
        const unsigned bal = __ballot_sync(0xffffffffu, pred);
        const int n = __popc(bal);
        if (cnt + n > 64) {
            knn_flush(S, lane);
            cnt = 17;
            tau = S[16];
        }
        if (pred) S[cnt + __popc(bal & ((1u << lane) - 1u))] = key;
        cnt += n;
    }
    if (cnt > 17) knn_flush(S, lane);

    if (lane < 16)
        g_nn[((size_t)b * RQ + r) * KQ + lane] =
            (int)(unsigned)(S[lane + 1] & 0xFFFFFFFFull);
}

// ---------------- kernel 3: gather + lift + T-net MLP + Tf, store Tf ----------------
#define MAIN_SMEM_FLOATS (4096 + 16 * 1288 + 768)
#define MAIN_SMEM_BYTES  (MAIN_SMEM_FLOATS * 4)
#define SF_OFF 4096
#define SP_OFF 24704

__global__ __launch_bounds__(256, 2) void mlp_kernel(
    const float* __restrict__ points,  const float* __restrict__ features,
    const float* __restrict__ lift_w,  const float* __restrict__ lift_b,
    const float* __restrict__ bnl_g,   const float* __restrict__ bnl_b,
    const float* __restrict__ t1_b,    const float* __restrict__ bn1_g,
    const float* __restrict__ bn1_b,   const float* __restrict__ t2_b,
    const float* __restrict__ bn2_g,   const float* __restrict__ bn2_b,
    const float* __restrict__ t3_b,    const float* __restrict__ bn3_g,
    const float* __restrict__ bn3_b,   const int* __restrict__ rep_idx,
    float* __restrict__ out_rep)
{
    extern __shared__ float sm[];
    float* sH = sm;
    float* sF = sm + SF_OFF;
    float* sP = sm + SP_OFF;
    const int tid = threadIdx.x;
    const int gg0 = blockIdx.x * 16;

    {
        const int g = tid >> 4, k = tid & 15;
        const int gg = gg0 + g;
        const int b = gg >> 11, rl = gg & 2047;
        const int rpt = __ldg(&rep_idx[rl]);
        const float* rpp = points + ((size_t)b * NQ + rpt) * 3;
        const float rx = __ldg(rpp), ry = __ldg(rpp + 1), rz = __ldg(rpp + 2);
        const int nb = g_nn[gg * KQ + k];
        const float* npp = points + ((size_t)b * NQ + nb) * 3;
        const float px = __ldg(npp) - rx, py = __ldg(npp + 1) - ry, pz = __ldg(npp + 2) - rz;
        sP[g * 48 + k * 3 + 0] = px;
        sP[g * 48 + k * 3 + 1] = py;
        sP[g * 48 + k * 3 + 2] = pz;
        if (k == 0) {
            out_rep[gg * 3 + 0] = rx; out_rep[gg * 3 + 1] = ry; out_rep[gg * 3 + 2] = rz;
        }
        float* fl = &sF[g * 1288 + k * 80];
#pragma unroll
        for (int j = 0; j < 16; j++) {
            float d = fmaf(pz, __ldg(&lift_w[j * 3 + 2]),
                      fmaf(py, __ldg(&lift_w[j * 3 + 1]), px * __ldg(&lift_w[j * 3 + 0])));
            float v = fmaf(d + __ldg(&lift_b[j]), __ldg(&bnl_g[j]), __ldg(&bnl_b[j]));
            fl[j] = fmaxf(v, 0.f);
        }
        const float4* fr = (const float4*)(features + ((size_t)b * NQ + nb) * 64);
        float4* fd = (float4*)(fl + 16);
#pragma unroll
        for (int q = 0; q < 16; q++) fd[q] = __ldg(fr + q);
    }
    __syncthreads();

    const int i = tid;
    float acc[16];

    // ---- t1: pf[16][48] @ W1^T -> H[16][256], bn+relu ----
    {
#pragma unroll
        for (int g2 = 0; g2 < 16; g2++) acc[g2] = 0.f;
#pragma unroll
        for (int jj = 0; jj < 12; ++jj) {
            const float4 w = __ldg((const float4*)&g_w1p[jj * 1024 + i * 4]);
#pragma unroll
            for (int g2 = 0; g2 < 16; ++g2) {
                const float4 h = *(const float4*)&sP[g2 * 48 + jj * 4];
                acc[g2] = fmaf(w.x, h.x, acc[g2]); acc[g2] = fmaf(w.y, h.y, acc[g2]);
                acc[g2] = fmaf(w.z, h.z, acc[g2]); acc[g2] = fmaf(w.w, h.w, acc[g2]);
            }
        }
        const float tb = __ldg(&t1_b[i]), bg = __ldg(&bn1_g[i]), bb = __ldg(&bn1_b[i]);
#pragma unroll
        for (int g2 = 0; g2 < 16; g2++)
            sH[g2 * 256 + i] = fmaxf(fmaf(acc[g2] + tb, bg, bb), 0.f);
    }
    __syncthreads();

    // ---- t2: H @ W2^T, bn+relu ----
    {
#pragma unroll
        for (int g2 = 0; g2 < 16; g2++) acc[g2] = 0.f;
#pragma unroll 4
        for (int jj = 0; jj < 64; ++jj) {
            const float4 w = __ldg((const float4*)&g_w2p[jj * 1024 + i * 4]);
#pragma unroll
            for (int g2 = 0; g2 < 16; ++g2) {
                const float4 h = *(const float4*)&sH[g2 * 256 + jj * 4];
                acc[g2] = fmaf(w.x, h.x, acc[g2]); acc[g2] = fmaf(w.y, h.y, acc[g2]);
                acc[g2] = fmaf(w.z, h.z, acc[g2]); acc[g2] = fmaf(w.w, h.w, acc[g2]);
            }
        }
        const float tb = __ldg(&t2_b[i]), bg = __ldg(&bn2_g[i]), bb = __ldg(&bn2_b[i]);
        __syncthreads();
#pragma unroll
        for (int g2 = 0; g2 < 16; g2++)
            sH[g2 * 256 + i] = fmaxf(fmaf(acc[g2] + tb, bg, bb), 0.f);
    }
    __syncthreads();

    // ---- t3: H @ W3^T, bn (no relu) -> T[16][16][16] in sH ----
    {
#pragma unroll
        for (int g2 = 0; g2 < 16; g2++) acc[g2] = 0.f;
#pragma unroll 4
        for (int jj = 0; jj < 64; ++jj) {
            const float4 w = __ldg((const float4*)&g_w3p[jj * 1024 + i * 4]);
#pragma unroll
            for (int g2 = 0; g2 < 16; ++g2) {
                const float4 h = *(const float4*)&sH[g2 * 256 + jj * 4];
                acc[g2] = fmaf(w.x, h.x, acc[g2]); acc[g2] = fmaf(w.y, h.y, acc[g2]);
                acc[g2] = fmaf(w.z, h.z, acc[g2]); acc[g2] = fmaf(w.w, h.w, acc[g2]);
            }
        }
        const float tb = __ldg(&t3_b[i]), bg = __ldg(&bn3_g[i]), bb = __ldg(&bn3_b[i]);
        __syncthreads();
#pragma unroll
        for (int g2 = 0; g2 < 16; g2++)
            sH[g2 * 256 + i] = fmaf(acc[g2] + tb, bg, bb);
    }
    __syncthreads();

    const int aT = tid & 15, gT = tid >> 4;
    float tr[16];
#pragma unroll
    for (int q = 0; q < 4; q++) {
        const float4 v = *(const float4*)&sH[gT * 256 + aT * 16 + q * 4];
        tr[q * 4 + 0] = v.x; tr[q * 4 + 1] = v.y; tr[q * 4 + 2] = v.z; tr[q * 4 + 3] = v.w;
    }
    __syncthreads();

    const int gw = tid >> 4;
    const int ow = (tid & 15) * 16;
#pragma unroll 1
    for (int cb = 0; cb < 5; ++cb) {
#pragma unroll
        for (int q = 0; q < 4; q++) {
            const int c0 = cb * 16 + q * 4;
            float sx = 0.f, sy = 0.f, sz = 0.f, sw2 = 0.f;
#pragma unroll
            for (int k = 0; k < 16; k++) {
                const float4 f = *(const float4*)&sF[gT * 1288 + k * 80 + c0];
                sx = fmaf(tr[k], f.x, sx); sy = fmaf(tr[k], f.y, sy);
                sz = fmaf(tr[k], f.z, sz); sw2 = fmaf(tr[k], f.w, sw2);
            }
            sH[gT * 256 + (q * 4 + 0) * 16 + aT] = sx;
            sH[gT * 256 + (q * 4 + 1) * 16 + aT] = sy;
            sH[gT * 256 + (q * 4 + 2) * 16 + aT] = sz;
            sH[gT * 256 + (q * 4 + 3) * 16 + aT] = sw2;
        }
        __syncthreads();
        {
            float4* dst = (float4*)&g_tf[(size_t)(gg0 + gw) * 1280 + cb * 256 + ow];
            const float4* src = (const float4*)&sH[gw * 256 + ow];
            dst[0] = src[0]; dst[1] = src[1]; dst[2] = src[2]; dst[3] = src[3];
        }
        __syncthreads();
    }
}

// ---------------- kernel 4: conv GEMM, split-K x8, 128x128 tile ----------------
// grid (32, 8): blockIdx.x = M-tile (128 rows), blockIdx.y = kz (160-K slice).
// 256 threads: tm = tid&15 (rows tm+16r), tn = (tid>>4)*8 (8 cols). 8x8 regs.
#define CV_KC   32
#define CV_SA_S 33
#define CONV_SMEM_BYTES ((128 * CV_SA_S + CV_KC * 128) * 4)

__global__ __launch_bounds__(256, 2) void conv_kernel(float* __restrict__ dummy) {
    extern __shared__ float sm[];
    float* sA = sm;                         // [128][33]  m-major
    float* sB = sm + 128 * CV_SA_S;         // [32][128]
    const int tid = threadIdx.x;
    const int gm0 = blockIdx.x * 128;
    const int kz  = blockIdx.y;
    const int k0z = kz * 160;

    const int tm = tid & 15;                // rows tm + 16*r
    const int tn = (tid >> 4) * 8;          // 8 cols

    float acc[8][8];
#pragma unroll
    for (int r = 0; r < 8; r++)
#pragma unroll
        for (int c = 0; c < 8; c++) acc[r][c] = 0.f;

#pragma unroll 1
    for (int kt = 0; kt < 160; kt += CV_KC) {
        const int kbase = k0z + kt;
        // load B tile [32][128]: 1024 float4, 4 per thread
#pragma unroll
        for (int q = 0; q < 4; ++q) {
            int idx = tid + q * 256;
            int j = idx >> 5, c4 = idx & 31;
            *(float4*)&sB[j * 128 + c4 * 4] =
                __ldg((const float4*)&g_wt[(size_t)(kbase + j) * 128 + c4 * 4]);
        }
        // load A tile [128][32]: 1024 float4, 4 per thread (m-major, stride 33)
#pragma unroll
        for (int q = 0; q < 4; ++q) {
            int idx = tid + q * 256;
            int m = idx >> 3, k4 = idx & 7;
            float4 v = __ldg((const float4*)&g_tf[(size_t)(gm0 + m) * 1280 + kbase + k4 * 4]);
            float* d = &sA[m * CV_SA_S + k4 * 4];
            d[0] = v.x; d[1] = v.y; d[2] = v.z; d[3] = v.w;
        }
        __syncthreads();

#pragma unroll 2
        for (int k = 0; k < CV_KC; ++k) {
            const float4 b0 = *(const float4*)&sB[k * 128 + tn];
            const float4 b1 = *(const float4*)&sB[k * 128 + tn + 4];
            float a[8];
#pragma unroll
            for (int r = 0; r < 8; r++) a[r] = sA[(tm + 16 * r) * CV_SA_S + k];
#pragma unroll
            for (int r = 0; r < 8; r++) {
                acc[r][0] = fmaf(a[r], b0.x, acc[r][0]);
                acc[r][1] = fmaf(a[r], b0.y, acc[r][1]);
                acc[r][2] = fmaf(a[r], b0.z, acc[r][2]);
                acc[r][3] = fmaf(a[r], b0.w, acc[r][3]);
                acc[r][4] = fmaf(a[r], b1.x, acc[r][4]);
                acc[r][5] = fmaf(a[r], b1.y, acc[r][5]);
                acc[r][6] = fmaf(a[r], b1.z, acc[r][6]);
                acc[r][7] = fmaf(a[r], b1.w, acc[r][7]);
            }
        }
        __syncthreads();
    }

    float* dst = &g_part[kz][0];
#pragma unroll
    for (int r = 0; r < 8; r++) {
        const int m = gm0 + tm + 16 * r;
        *(float4*)&dst[(size_t)m * 128 + tn] =
            make_float4(acc[r][0], acc[r][1], acc[r][2], acc[r][3]);
        *(float4*)&dst[(size_t)m * 128 + tn + 4] =
            make_float4(acc[r][4], acc[r][5], acc[r][6], acc[r][7]);
    }
    (void)dummy;
}

// ---------------- kernel 5: split-K reduce + bias ----------------
__global__ void reduce_kernel(const float* __restrict__ conv_b,
                              float* __restrict__ out_main) {
    int t = blockIdx.x * 256 + threadIdx.x;      // float4 index, 131072 total
    int o4 = (t & 31) * 4;
    float4 s = *(const float4*)&g_part[0][(size_t)t * 4];
#pragma unroll
    for (int z = 1; z < 8; ++z) {
        const float4 p = *(const float4*)&g_part[z][(size_t)t * 4];
        s.x += p.x; s.y += p.y; s.z += p.z; s.w += p.w;
    }
    const float4 cb = __ldg((const float4*)&conv_b[o4]);
    s.x += cb.x; s.y += cb.y; s.z += cb.z; s.w += cb.w;
    *(float4*)&out_main[(size_t)t * 4] = s;
}

// ---------------- launch ----------------
extern "C" void kernel_launch(void* const* d_in, const int* in_sizes, int n_in,
                              void* d_out, int out_size) {
    (void)in_sizes; (void)n_in; (void)out_size;
    const float* points   = (const float*)d_in[0];
    const float* features = (const float*)d_in[1];
    const float* lift_w   = (const float*)d_in[2];
    const float* lift_b   = (const float*)d_in[3];
    const float* bnl_g    = (const float*)d_in[4];
    const float* bnl_b    = (const float*)d_in[5];
    const float* t1_w     = (const float*)d_in[6];
    const float* t1_b     = (const float*)d_in[7];
    const float* bn1_g    = (const float*)d_in[8];
    const float* bn1_b    = (const float*)d_in[9];
    const float* t2_w     = (const float*)d_in[10];
    const float* t2_b     = (const float*)d_in[11];
    const float* bn2_g    = (const float*)d_in[12];
    const float* bn2_b    = (const float*)d_in[13];
    const float* t3_w     = (const float*)d_in[14];
    const float* t3_b     = (const float*)d_in[15];
    const float* bn3_g    = (const float*)d_in[16];
    const float* bn3_b    = (const float*)d_in[17];
    const float* conv_w   = (const float*)d_in[18];
    const float* conv_b   = (const float*)d_in[19];
    const int*   rep_idx  = (const int*)d_in[20];

    float* out      = (float*)d_out;
    float* out_rep  = out;                       // [B][R][3]
    float* out_main = out + BQ * RQ * 3;         // [B][R][128]

    cudaFuncSetAttribute(mlp_kernel,  cudaFuncAttributeMaxDynamicSharedMemorySize, MAIN_SMEM_BYTES);
    cudaFuncSetAttribute(conv_kernel, cudaFuncAttributeMaxDynamicSharedMemorySize, CONV_SMEM_BYTES);

    prep_kernel<<<(PREP_TOTAL + 255) / 256, 256>>>(points, t1_w, t2_w, t3_w, conv_w);
    knn_kernel<<<dim3(128, 2), 512>>>(rep_idx);
    mlp_kernel<<<256, 256, MAIN_SMEM_BYTES>>>(
        points, features, lift_w, lift_b, bnl_g, bnl_b,
        t1_b, bn1_g, bn1_b, t2_b, bn2_g, bn2_b,
        t3_b, bn3_g, bn3_b, rep_idx, out_rep);
    conv_kernel<<<dim3(32, 8), 256, CONV_SMEM_BYTES>>>(nullptr);
    reduce_kernel<<<512, 256>>>(conv_b, out_main);
}